// round 7
// baseline (speedup 1.0000x reference)
#include <cuda_runtime.h>
#include <cuda_bf16.h>
#include <cstdint>
#include <math.h>

#define Bsz 32
#define Nn  1024
#define Dd  128
#define NROWS (Bsz*Nn)

// Scratch (device globals: allocation-free rule)
__device__ float g_itr[NROWS * Dd];          // itr_attn fp32
__device__ float g_qa[NROWS];                // qa[j] = P[j].wa
__device__ uint32_t g_whu[3 * 16384];        // weights bf16x2 hi (3 x 256x128)
__device__ uint32_t g_wlu[3 * 16384];        // weights bf16x2 lo

// ===========================================================================
// helpers
// ===========================================================================
__device__ __forceinline__ uint32_t smem_u32(const void* p) {
    uint32_t a;
    asm("{ .reg .u64 t; cvta.to.shared.u64 t, %1; cvt.u32.u64 %0, t; }" : "=r"(a) : "l"(p));
    return a;
}
__device__ __forceinline__ void ldsm_x4(uint32_t a[4], uint32_t addr) {
    asm volatile("ldmatrix.sync.aligned.m8n8.x4.shared.b16 {%0,%1,%2,%3}, [%4];"
        : "=r"(a[0]), "=r"(a[1]), "=r"(a[2]), "=r"(a[3]) : "r"(addr));
}
__device__ __forceinline__ void ldsm_x4t(uint32_t a[4], uint32_t addr) {
    asm volatile("ldmatrix.sync.aligned.m8n8.x4.trans.shared.b16 {%0,%1,%2,%3}, [%4];"
        : "=r"(a[0]), "=r"(a[1]), "=r"(a[2]), "=r"(a[3]) : "r"(addr));
}
__device__ __forceinline__ void mma_bf16(float c[4], const uint32_t a[4], const uint32_t b[2]) {
    asm volatile("mma.sync.aligned.m16n8k16.row.col.f32.bf16.bf16.f32 "
        "{%0,%1,%2,%3}, {%4,%5,%6,%7}, {%8,%9}, {%0,%1,%2,%3};"
        : "+f"(c[0]), "+f"(c[1]), "+f"(c[2]), "+f"(c[3])
        : "r"(a[0]), "r"(a[1]), "r"(a[2]), "r"(a[3]), "r"(b[0]), "r"(b[1]));
}
// pack two floats -> bf16x2 (hi) and residual bf16x2 (lo)
__device__ __forceinline__ void split2(float x, float y, uint32_t& h, uint32_t& l) {
    __nv_bfloat16 hx = __float2bfloat16_rn(x), hy = __float2bfloat16_rn(y);
    __nv_bfloat162 hv = __halves2bfloat162(hx, hy);
    h = *(uint32_t*)&hv;
    __nv_bfloat162 lv = __halves2bfloat162(
        __float2bfloat16_rn(x - __bfloat162float(hx)),
        __float2bfloat16_rn(y - __bfloat162float(hy)));
    l = *(uint32_t*)&lv;
}

// ===========================================================================
// prep kernels
// ===========================================================================
__global__ void qa_kernel(const float* __restrict__ P, const float* __restrict__ w) {
    int row  = blockIdx.x * blockDim.y + threadIdx.y;
    int lane = threadIdx.x;
    if (row >= NROWS) return;
    const float* p = P + (size_t)row * Dd;
    float s = 0.f;
    #pragma unroll
    for (int k = lane; k < Dd; k += 32) s += p[k] * w[k];
    #pragma unroll
    for (int off = 16; off > 0; off >>= 1) s += __shfl_xor_sync(0xffffffffu, s, off);
    if (lane == 0) g_qa[row] = s;
}

// split w1/w2/w3 (256x128 f32, n-contiguous) into bf16x2 hi/lo pairs along n
__global__ void wsplit_kernel(const float* __restrict__ w1, const float* __restrict__ w2,
                              const float* __restrict__ w3) {
    int idx = blockIdx.x * 256 + threadIdx.x;    // 16384 u32 per weight
    if (idx >= 16384) return;
    const float* srcs[3] = { w1, w2, w3 };
    #pragma unroll
    for (int g = 0; g < 3; g++) {
        float x = srcs[g][idx * 2], y = srcs[g][idx * 2 + 1];
        uint32_t h, l;
        split2(x, y, h, l);
        g_whu[g * 16384 + idx] = h;
        g_wlu[g * 16384 + idx] = l;
    }
}

// ===========================================================================
// HMMA flash attention, occupancy-tuned: BM=64, BN=64, 128 threads, 4 warps,
// smem 69.9KB, __launch_bounds__(128,3) -> 3 CTAs/SM (12 warps/SM).
// S = (P*wc) @ P^T (+qa[j]); no-max softmax; probs stay in regs; K tile
// doubles as V via trans ldsm; bf16 hi/lo 3-term split, k-tile outer.
// ===========================================================================
#define LDT 136                              // bf16 tile stride (conflict-free)
#define FS_QH 0
#define FS_QL 17408
#define FS_KH 34816
#define FS_KL 52224
#define FS_QA 69632
#define FS_TOT 69888

__global__ __launch_bounds__(128, 3)
void flash_hmma(const float* __restrict__ P, const float* __restrict__ w) {
    extern __shared__ char smem[];
    const uint32_t sb = smem_u32(smem);
    float* qas = (float*)(smem + FS_QA);
    const int tid = threadIdx.x, lane = tid & 31, wm = tid >> 5;
    const int b = blockIdx.y, i0 = blockIdx.x * 64;
    const int lg = lane >> 3, li = lane & 7;
    const int qr = lane >> 2, qc2 = (lane & 3) << 1;

    // ---- convert Q = P*wc into bf16 hi/lo tiles (64 rows) ----
    {
        const int r = tid >> 1, ch = (tid & 1) << 6;
        const float4* src = (const float4*)(P + ((size_t)(b * Nn + i0 + r)) * Dd + ch);
        const float4* wc4 = (const float4*)(w + 2 * Dd + ch);
        #pragma unroll
        for (int c4 = 0; c4 < 16; c4++) {
            float4 v = src[c4], wv = wc4[c4];
            int c0 = ch + c4 * 4;
            uint32_t h, l;
            split2(v.x * wv.x, v.y * wv.y, h, l);
            *(uint32_t*)(smem + FS_QH + (r * LDT + c0) * 2) = h;
            *(uint32_t*)(smem + FS_QL + (r * LDT + c0) * 2) = l;
            split2(v.z * wv.z, v.w * wv.w, h, l);
            *(uint32_t*)(smem + FS_QH + (r * LDT + c0 + 2) * 2) = h;
            *(uint32_t*)(smem + FS_QL + (r * LDT + c0 + 2) * 2) = l;
        }
    }

    float o[16][4];
    #pragma unroll
    for (int n = 0; n < 16; n++)
        #pragma unroll
        for (int u = 0; u < 4; u++) o[n][u] = 0.f;
    float lsum0 = 0.f, lsum1 = 0.f;

    for (int j0 = 0; j0 < Nn; j0 += 64) {
        __syncthreads();   // prior compute done (and Q visible on iter 0)
        // ---- convert K tile (64 keys, token-major bf16 hi/lo) ----
        {
            const int r = tid >> 1, ch = (tid & 1) << 6;
            const float4* src = (const float4*)(P + ((size_t)(b * Nn + j0 + r)) * Dd + ch);
            #pragma unroll
            for (int c4 = 0; c4 < 16; c4++) {
                float4 v = src[c4];
                int c0 = ch + c4 * 4;
                uint32_t h, l;
                split2(v.x, v.y, h, l);
                *(uint32_t*)(smem + FS_KH + (r * LDT + c0) * 2) = h;
                *(uint32_t*)(smem + FS_KL + (r * LDT + c0) * 2) = l;
                split2(v.z, v.w, h, l);
                *(uint32_t*)(smem + FS_KH + (r * LDT + c0 + 2) * 2) = h;
                *(uint32_t*)(smem + FS_KL + (r * LDT + c0 + 2) * 2) = l;
            }
            if (tid < 64) qas[tid] = g_qa[(size_t)b * Nn + j0 + tid];
        }
        __syncthreads();

        // ---- S = Q @ K^T, k-tile outer, terms QhKh + QlKh + QhKl ----
        float s[8][4];
        #pragma unroll
        for (int n = 0; n < 8; n++)
            #pragma unroll
            for (int u = 0; u < 4; u++) s[n][u] = 0.f;

        #pragma unroll
        for (int kt = 0; kt < 8; kt++) {
            const int arow = wm * 16 + ((lg & 1) << 3) + li;
            const int acol = kt * 16 + ((lg >> 1) << 3);
            uint32_t ah[4], al[4];
            ldsm_x4(ah, sb + FS_QH + (arow * LDT + acol) * 2);
            ldsm_x4(al, sb + FS_QL + (arow * LDT + acol) * 2);

            const int brow = ((lg >> 1) << 3) + li;
            const int bcol = kt * 16 + ((lg & 1) << 3);
            uint32_t bh[4][4];
            #pragma unroll
            for (int jp = 0; jp < 4; jp++)
                ldsm_x4(bh[jp], sb + FS_KH + ((jp * 16 + brow) * LDT + bcol) * 2);
            #pragma unroll
            for (int jp = 0; jp < 4; jp++) {
                mma_bf16(s[2 * jp],     ah, bh[jp]);
                mma_bf16(s[2 * jp + 1], ah, bh[jp] + 2);
            }
            #pragma unroll
            for (int jp = 0; jp < 4; jp++) {
                mma_bf16(s[2 * jp],     al, bh[jp]);
                mma_bf16(s[2 * jp + 1], al, bh[jp] + 2);
            }
            #pragma unroll
            for (int jp = 0; jp < 4; jp++) {
                uint32_t bl[4];
                ldsm_x4(bl, sb + FS_KL + ((jp * 16 + brow) * LDT + bcol) * 2);
                mma_bf16(s[2 * jp],     ah, bl);
                mma_bf16(s[2 * jp + 1], ah, bl + 2);
            }
        }

        // ---- exp (+qa col bias), pack probs into PV A-fragments ----
        uint32_t ph[4][4], pl[4][4];
        #pragma unroll
        for (int jn = 0; jn < 8; jn++) {
            int cb = jn * 8 + qc2;
            float q0 = qas[cb], q1 = qas[cb + 1];
            float p0 = __expf(s[jn][0] + q0);
            float p1 = __expf(s[jn][1] + q1);
            float p2 = __expf(s[jn][2] + q0);
            float p3 = __expf(s[jn][3] + q1);
            lsum0 += p0 + p1;
            lsum1 += p2 + p3;
            int kt = jn >> 1, hv = (jn & 1) << 1;
            split2(p0, p1, ph[kt][hv],     pl[kt][hv]);
            split2(p2, p3, ph[kt][hv + 1], pl[kt][hv + 1]);
        }

        // ---- O += P @ V (V tile == K tile via trans ldsm), k-tile outer ----
        #pragma unroll
        for (int kt = 0; kt < 4; kt++) {
            const int brow = kt * 16 + ((lg & 1) << 3) + li;
            const int bcol = (lg >> 1) << 3;
            uint32_t bh[8][4];
            #pragma unroll
            for (int dp = 0; dp < 8; dp++)
                ldsm_x4t(bh[dp], sb + FS_KH + (brow * LDT + dp * 16 + bcol) * 2);
            #pragma unroll
            for (int dp = 0; dp < 8; dp++) {
                mma_bf16(o[2 * dp],     ph[kt], bh[dp]);
                mma_bf16(o[2 * dp + 1], ph[kt], bh[dp] + 2);
            }
            #pragma unroll
            for (int dp = 0; dp < 8; dp++) {
                mma_bf16(o[2 * dp],     pl[kt], bh[dp]);
                mma_bf16(o[2 * dp + 1], pl[kt], bh[dp] + 2);
            }
            #pragma unroll
            for (int dp = 0; dp < 8; dp++) {
                uint32_t bl[4];
                ldsm_x4t(bl, sb + FS_KL + (brow * LDT + dp * 16 + bcol) * 2);
                mma_bf16(o[2 * dp],     ph[kt], bl);
                mma_bf16(o[2 * dp + 1], ph[kt], bl + 2);
            }
        }
    }

    // ---- normalize, store itr ----
    lsum0 += __shfl_xor_sync(0xffffffffu, lsum0, 1);
    lsum0 += __shfl_xor_sync(0xffffffffu, lsum0, 2);
    lsum1 += __shfl_xor_sync(0xffffffffu, lsum1, 1);
    lsum1 += __shfl_xor_sync(0xffffffffu, lsum1, 2);
    float inv0 = 1.f / lsum0, inv1 = 1.f / lsum1;
    const size_t r0 = (size_t)b * Nn + i0 + wm * 16 + qr;
    #pragma unroll
    for (int dn = 0; dn < 16; dn++) {
        int c = dn * 8 + qc2;
        *(float2*)(g_itr + r0 * Dd + c)       = make_float2(o[dn][0] * inv0, o[dn][1] * inv0);
        *(float2*)(g_itr + (r0 + 8) * Dd + c) = make_float2(o[dn][2] * inv1, o[dn][3] * inv1);
    }
}

// ===========================================================================
// HMMA fused gated MLP, occupancy-tuned: 128 threads, 4 warps (2x2),
// 32 rows/CTA, W streamed in k-chunks of 64, gates sequential with
// incremental epilogue (z then r*P then out). smem 68.6KB -> 3 CTAs/SM.
// ===========================================================================
#define XLD 264
#define MS_XH 0
#define MS_XL 16896
#define MS_WH 33792
#define MS_WL 51200
#define MS_TOT 68608

__global__ __launch_bounds__(128, 3)
void mlp_hmma(const float* __restrict__ P,
              const float* __restrict__ b1, const float* __restrict__ b2,
              const float* __restrict__ b3, float* __restrict__ out) {
    extern __shared__ char smem[];
    const uint32_t sb = smem_u32(smem);
    const int tid = threadIdx.x, lane = tid & 31, wid = tid >> 5;
    const int wm = wid & 1, wn = wid >> 1;
    const int lg = lane >> 3, li = lane & 7;
    const int qr = lane >> 2, qc2 = (lane & 3) << 1;
    const int row0 = blockIdx.x * 32;

    // ---- convert X = [P | itr] into bf16 hi/lo (32 x 256) ----
    {
        const int r = tid >> 2, q = tid & 3;
        const int c0 = q * 64;
        const float* base = (q < 2)
            ? (P     + ((size_t)(row0 + r)) * Dd + q * 64)
            : (g_itr + ((size_t)(row0 + r)) * Dd + (q - 2) * 64);
        const float4* src = (const float4*)base;
        #pragma unroll
        for (int c4 = 0; c4 < 16; c4++) {
            float4 v = src[c4];
            int c = c0 + c4 * 4;
            uint32_t h, l;
            split2(v.x, v.y, h, l);
            *(uint32_t*)(smem + MS_XH + (r * XLD + c) * 2) = h;
            *(uint32_t*)(smem + MS_XL + (r * XLD + c) * 2) = l;
            split2(v.z, v.w, h, l);
            *(uint32_t*)(smem + MS_XH + (r * XLD + c + 2) * 2) = h;
            *(uint32_t*)(smem + MS_XL + (r * XLD + c + 2) * 2) = l;
        }
    }

    float zf[8][4], rp[8][4];

    #pragma unroll 1
    for (int g = 0; g < 3; g++) {
        float acc[8][4];
        #pragma unroll
        for (int n = 0; n < 8; n++)
            #pragma unroll
            for (int u = 0; u < 4; u++) acc[n][u] = 0.f;

        #pragma unroll 1
        for (int kc = 0; kc < 4; kc++) {
            __syncthreads();   // X ready (first iter) / prior W reads done
            // load W chunk (64 k-rows x 128 n), hi/lo, u32 stride 68
            {
                const uint32_t* wh = g_whu + g * 16384 + kc * 4096;
                const uint32_t* wl = g_wlu + g * 16384 + kc * 4096;
                uint32_t* dh = (uint32_t*)(smem + MS_WH);
                uint32_t* dl = (uint32_t*)(smem + MS_WL);
                #pragma unroll 4
                for (int t = 0; t < 32; t++) {
                    int idx = tid + t * 128;            // 4096 u32
                    int r = idx >> 6, c = idx & 63;
                    dh[r * 68 + c] = wh[idx];
                    dl[r * 68 + c] = wl[idx];
                }
            }
            __syncthreads();

            #pragma unroll
            for (int kt = 0; kt < 4; kt++) {
                const int ktg = kc * 4 + kt;
                const int arow = wm * 16 + ((lg & 1) << 3) + li;
                const int acol = ktg * 16 + ((lg >> 1) << 3);
                uint32_t ah[4], al[4];
                ldsm_x4(ah, sb + MS_XH + (arow * XLD + acol) * 2);
                ldsm_x4(al, sb + MS_XL + (arow * XLD + acol) * 2);

                const int brow = kt * 16 + ((lg & 1) << 3) + li;
                const int bcol = wn * 64 + ((lg >> 1) << 3);
                uint32_t bh[4][4];
                #pragma unroll
                for (int np = 0; np < 4; np++)
                    ldsm_x4t(bh[np], sb + MS_WH + (brow * 136 + np * 16 + bcol) * 2);
                #pragma unroll
                for (int np = 0; np < 4; np++) {
                    mma_bf16(acc[2 * np],     ah, bh[np]);
                    mma_bf16(acc[2 * np + 1], ah, bh[np] + 2);
                }
                #pragma unroll
                for (int np = 0; np < 4; np++) {
                    mma_bf16(acc[2 * np],     al, bh[np]);
                    mma_bf16(acc[2 * np + 1], al, bh[np] + 2);
                }
                #pragma unroll
                for (int np = 0; np < 4; np++) {
                    uint32_t bl[4];
                    ldsm_x4t(bl, sb + MS_WL + (brow * 136 + np * 16 + bcol) * 2);
                    mma_bf16(acc[2 * np],     ah, bl);
                    mma_bf16(acc[2 * np + 1], ah, bl + 2);
                }
            }
        }

        // ---- per-gate incremental epilogue ----
        if (g == 0) {
            #pragma unroll
            for (int n = 0; n < 8; n++) {
                int c = wn * 64 + n * 8 + qc2;
                float bx = b1[c], by = b1[c + 1];
                zf[n][0] = tanhf(acc[n][0] + bx);
                zf[n][1] = tanhf(acc[n][1] + by);
                zf[n][2] = tanhf(acc[n][2] + bx);
                zf[n][3] = tanhf(acc[n][3] + by);
            }
        } else if (g == 1) {
            #pragma unroll
            for (int n = 0; n < 8; n++) {
                int c = wn * 64 + n * 8 + qc2;
                float bx = b2[c], by = b2[c + 1];
                #pragma unroll
                for (int half = 0; half < 2; half++) {
                    size_t r = (size_t)row0 + wm * 16 + qr + half * 8;
                    float2 pv = *(const float2*)(P + r * Dd + c);
                    rp[n][half * 2]     = pv.x / (1.f + __expf(-(acc[n][half * 2]     + bx)));
                    rp[n][half * 2 + 1] = pv.y / (1.f + __expf(-(acc[n][half * 2 + 1] + by)));
                }
            }
        } else {
            #pragma unroll
            for (int n = 0; n < 8; n++) {
                int c = wn * 64 + n * 8 + qc2;
                float bx = b3[c], by = b3[c + 1];
                #pragma unroll
                for (int half = 0; half < 2; half++) {
                    size_t r = (size_t)row0 + wm * 16 + qr + half * 8;
                    float fx = 1.f / (1.f + __expf(-(acc[n][half * 2]     + bx)));
                    float fy = 1.f / (1.f + __expf(-(acc[n][half * 2 + 1] + by)));
                    *(float2*)(out + r * Dd + c) = make_float2(
                        rp[n][half * 2]     + fx * zf[n][half * 2],
                        rp[n][half * 2 + 1] + fy * zf[n][half * 2 + 1]);
                }
            }
        }
    }
}

// ===========================================================================
extern "C" void kernel_launch(void* const* d_in, const int* in_sizes, int n_in,
                              void* d_out, int out_size) {
    const float* P  = (const float*)d_in[0];
    const float* w  = (const float*)d_in[1];
    const float* w1 = (const float*)d_in[2];
    const float* w2 = (const float*)d_in[3];
    const float* w3 = (const float*)d_in[4];
    const float* b1 = (const float*)d_in[5];
    const float* b2 = (const float*)d_in[6];
    const float* b3 = (const float*)d_in[7];
    float* out = (float*)d_out;

    cudaFuncSetAttribute(flash_hmma, cudaFuncAttributeMaxDynamicSharedMemorySize, FS_TOT);
    cudaFuncSetAttribute(mlp_hmma, cudaFuncAttributeMaxDynamicSharedMemorySize, MS_TOT);

    wsplit_kernel<<<64, 256>>>(w1, w2, w3);

    dim3 qb(32, 8);
    qa_kernel<<<NROWS / 8, qb>>>(P, w);

    dim3 fg(Nn / 64, Bsz);
    flash_hmma<<<fg, 128, FS_TOT>>>(P, w);

    mlp_hmma<<<NROWS / 32, 128, MS_TOT>>>(P, b1, b2, b3, out);
}

// round 8
// speedup vs baseline: 1.4993x; 1.4993x over previous
#include <cuda_runtime.h>
#include <cuda_bf16.h>
#include <cstdint>
#include <math.h>

#define Bsz 32
#define Nn  1024
#define Dd  128
#define NROWS (Bsz*Nn)

// Scratch (device globals: allocation-free rule). All u32 = bf16x2 pairs.
__device__ float    g_qa[NROWS];             // qa[j] = P[j].wa
__device__ uint32_t g_Qh[NROWS * 64];        // (P*wc) hi
__device__ uint32_t g_Ql[NROWS * 64];        // (P*wc) lo
__device__ uint32_t g_Ph[NROWS * 64];        // P hi
__device__ uint32_t g_Pl[NROWS * 64];        // P lo
__device__ uint32_t g_Ih[NROWS * 64];        // itr hi
__device__ uint32_t g_Il[NROWS * 64];        // itr lo
__device__ uint32_t g_whu[3 * 16384];        // weights hi (3 x 256x128)
__device__ uint32_t g_wlu[3 * 16384];        // weights lo

// ===========================================================================
// helpers
// ===========================================================================
__device__ __forceinline__ uint32_t smem_u32(const void* p) {
    uint32_t a;
    asm("{ .reg .u64 t; cvta.to.shared.u64 t, %1; cvt.u32.u64 %0, t; }" : "=r"(a) : "l"(p));
    return a;
}
__device__ __forceinline__ void ldsm_x4(uint32_t a[4], uint32_t addr) {
    asm volatile("ldmatrix.sync.aligned.m8n8.x4.shared.b16 {%0,%1,%2,%3}, [%4];"
        : "=r"(a[0]), "=r"(a[1]), "=r"(a[2]), "=r"(a[3]) : "r"(addr));
}
__device__ __forceinline__ void ldsm_x4t(uint32_t a[4], uint32_t addr) {
    asm volatile("ldmatrix.sync.aligned.m8n8.x4.trans.shared.b16 {%0,%1,%2,%3}, [%4];"
        : "=r"(a[0]), "=r"(a[1]), "=r"(a[2]), "=r"(a[3]) : "r"(addr));
}
__device__ __forceinline__ void mma_bf16(float c[4], const uint32_t a[4], const uint32_t b[2]) {
    asm volatile("mma.sync.aligned.m16n8k16.row.col.f32.bf16.bf16.f32 "
        "{%0,%1,%2,%3}, {%4,%5,%6,%7}, {%8,%9}, {%0,%1,%2,%3};"
        : "+f"(c[0]), "+f"(c[1]), "+f"(c[2]), "+f"(c[3])
        : "r"(a[0]), "r"(a[1]), "r"(a[2]), "r"(a[3]), "r"(b[0]), "r"(b[1]));
}
__device__ __forceinline__ void split2(float x, float y, uint32_t& h, uint32_t& l) {
    __nv_bfloat16 hx = __float2bfloat16_rn(x), hy = __float2bfloat16_rn(y);
    __nv_bfloat162 hv = __halves2bfloat162(hx, hy);
    h = *(uint32_t*)&hv;
    __nv_bfloat162 lv = __halves2bfloat162(
        __float2bfloat16_rn(x - __bfloat162float(hx)),
        __float2bfloat16_rn(y - __bfloat162float(hy)));
    l = *(uint32_t*)&lv;
}
__device__ __forceinline__ void cpa16(uint32_t dst, const void* src) {
    asm volatile("cp.async.cg.shared.global [%0], [%1], 16;" :: "r"(dst), "l"(src));
}
#define CP_COMMIT()  asm volatile("cp.async.commit_group;" ::: "memory")
#define CP_WAIT0()   asm volatile("cp.async.wait_group 0;" ::: "memory")

// ===========================================================================
// prep: per row -> qa dot, and bf16 hi/lo planes for P and Q=P*wc
// ===========================================================================
__global__ void prep_kernel(const float* __restrict__ P, const float* __restrict__ w) {
    const int row  = blockIdx.x * 8 + (threadIdx.x >> 5);
    const int lane = threadIdx.x & 31;
    const float4 p  = *(const float4*)(P + (size_t)row * Dd + lane * 4);
    const float4 wa = *(const float4*)(w + lane * 4);
    const float4 wc = *(const float4*)(w + 2 * Dd + lane * 4);
    float s = p.x * wa.x + p.y * wa.y + p.z * wa.z + p.w * wa.w;
    #pragma unroll
    for (int off = 16; off > 0; off >>= 1) s += __shfl_xor_sync(0xffffffffu, s, off);
    if (lane == 0) g_qa[row] = s;
    const size_t o = (size_t)row * 64 + lane * 2;
    uint32_t h, l;
    split2(p.x, p.y, h, l);             g_Ph[o] = h;     g_Pl[o] = l;
    split2(p.z, p.w, h, l);             g_Ph[o + 1] = h; g_Pl[o + 1] = l;
    split2(p.x * wc.x, p.y * wc.y, h, l); g_Qh[o] = h;     g_Ql[o] = l;
    split2(p.z * wc.z, p.w * wc.w, h, l); g_Qh[o + 1] = h; g_Ql[o + 1] = l;
}

// split w1/w2/w3 (256x128 f32) into bf16x2 hi/lo
__global__ void wsplit_kernel(const float* __restrict__ w1, const float* __restrict__ w2,
                              const float* __restrict__ w3) {
    int idx = blockIdx.x * 256 + threadIdx.x;
    if (idx >= 16384) return;
    const float* srcs[3] = { w1, w2, w3 };
    #pragma unroll
    for (int g = 0; g < 3; g++) {
        float x = srcs[g][idx * 2], y = srcs[g][idx * 2 + 1];
        uint32_t h, l;
        split2(x, y, h, l);
        g_whu[g * 16384 + idx] = h;
        g_wlu[g * 16384 + idx] = l;
    }
}

// ===========================================================================
// HMMA flash attention (BM=128, BN=128, 256 thr). No in-loop conversion:
// operand planes precomputed; K tiles double-buffered via cp.async.
// S = Qsplit @ Ksplit^T (+qa[j]); no-max softmax; probs in regs;
// K tile doubles as V via trans ldsm. Epilogue emits itr bf16 hi/lo.
// ===========================================================================
#define LDT 136
// smem byte offsets
#define FQH  0
#define FQL  34816
#define FK0  69632            // [KH 34816 | KL 34816]
#define FK1  139264
#define FQA0 208896           // 512 B
#define FQA1 209408
#define FTOT 209920

__device__ __forceinline__ void copy_tile_pair(uint32_t dstHi, uint32_t dstLo,
        const uint32_t* __restrict__ srcHi, const uint32_t* __restrict__ srcLo,
        size_t grow0, int tid) {
    #pragma unroll
    for (int t = 0; t < 8; t++) {
        int idx = tid + t * 256;             // 2048 16B-chunks (128 rows x 16)
        int r = idx >> 4, c8 = idx & 15;
        uint32_t doff = (uint32_t)(r * LDT + c8 * 8) * 2;
        cpa16(dstHi + doff, srcHi + (grow0 + r) * 64 + c8 * 4);
        cpa16(dstLo + doff, srcLo + (grow0 + r) * 64 + c8 * 4);
    }
}

__global__ __launch_bounds__(256, 1)
void flash_hmma() {
    extern __shared__ char smem[];
    const uint32_t sb = smem_u32(smem);
    const int tid = threadIdx.x, lane = tid & 31, wm = tid >> 5;
    const int b = blockIdx.y, i0 = blockIdx.x * 128;
    const int lg = lane >> 3, li = lane & 7;
    const int qr = lane >> 2, qc2 = (lane & 3) << 1;
    const size_t brow0 = (size_t)b * Nn;

    // preload Q tiles + K tile 0 + qa chunk 0
    copy_tile_pair(sb + FQH, sb + FQL, g_Qh, g_Ql, brow0 + i0, tid);
    copy_tile_pair(sb + FK0, sb + FK0 + 34816, g_Ph, g_Pl, brow0, tid);
    if (tid < 32) cpa16(sb + FQA0 + tid * 16, g_qa + brow0 + tid * 4);
    CP_COMMIT();
    CP_WAIT0();
    __syncthreads();

    float o[16][4];
    #pragma unroll
    for (int n = 0; n < 16; n++)
        #pragma unroll
        for (int u = 0; u < 4; u++) o[n][u] = 0.f;
    float lsum0 = 0.f, lsum1 = 0.f;

    for (int jt = 0; jt < 8; jt++) {
        const int cur = jt & 1;
        const uint32_t KH = sb + (cur ? FK1 : FK0);
        const uint32_t KL = KH + 34816;
        const float* qas = (const float*)(smem + (cur ? FQA1 : FQA0));

        // prefetch next tile into other buffer (overlapped with mma below)
        if (jt < 7) {
            const uint32_t NKH = sb + (cur ? FK0 : FK1);
            copy_tile_pair(NKH, NKH + 34816, g_Ph, g_Pl, brow0 + (jt + 1) * 128, tid);
            if (tid < 32)
                cpa16(sb + (cur ? FQA0 : FQA1) + tid * 16, g_qa + brow0 + (jt + 1) * 128 + tid * 4);
            CP_COMMIT();
        }

        // ---- S = Q @ K^T, k-tile outer, terms QhKh + QlKh + QhKl ----
        float s[16][4];
        #pragma unroll
        for (int n = 0; n < 16; n++)
            #pragma unroll
            for (int u = 0; u < 4; u++) s[n][u] = 0.f;

        #pragma unroll
        for (int kt = 0; kt < 8; kt++) {
            const int arow = wm * 16 + ((lg & 1) << 3) + li;
            const int acol = kt * 16 + ((lg >> 1) << 3);
            uint32_t ah[4], al[4];
            ldsm_x4(ah, sb + FQH + (arow * LDT + acol) * 2);
            ldsm_x4(al, sb + FQL + (arow * LDT + acol) * 2);

            const int brw = ((lg >> 1) << 3) + li;
            const int bcl = kt * 16 + ((lg & 1) << 3);
            uint32_t bh[8][4];
            #pragma unroll
            for (int jp = 0; jp < 8; jp++)
                ldsm_x4(bh[jp], KH + ((jp * 16 + brw) * LDT + bcl) * 2);
            #pragma unroll
            for (int jp = 0; jp < 8; jp++) {
                mma_bf16(s[2 * jp],     ah, bh[jp]);
                mma_bf16(s[2 * jp + 1], ah, bh[jp] + 2);
            }
            #pragma unroll
            for (int jp = 0; jp < 8; jp++) {
                mma_bf16(s[2 * jp],     al, bh[jp]);
                mma_bf16(s[2 * jp + 1], al, bh[jp] + 2);
            }
            #pragma unroll
            for (int jp = 0; jp < 8; jp++) {
                uint32_t bl[4];
                ldsm_x4(bl, KL + ((jp * 16 + brw) * LDT + bcl) * 2);
                mma_bf16(s[2 * jp],     ah, bl);
                mma_bf16(s[2 * jp + 1], ah, bl + 2);
            }
        }

        // ---- exp (+qa col bias), pack probs into PV A-fragments ----
        uint32_t ph[8][4], pl[8][4];
        #pragma unroll
        for (int jn = 0; jn < 16; jn++) {
            int cb = jn * 8 + qc2;
            float q0 = qas[cb], q1 = qas[cb + 1];
            float p0 = __expf(s[jn][0] + q0);
            float p1 = __expf(s[jn][1] + q1);
            float p2 = __expf(s[jn][2] + q0);
            float p3 = __expf(s[jn][3] + q1);
            lsum0 += p0 + p1;
            lsum1 += p2 + p3;
            int kt = jn >> 1, hv = (jn & 1) << 1;
            split2(p0, p1, ph[kt][hv],     pl[kt][hv]);
            split2(p2, p3, ph[kt][hv + 1], pl[kt][hv + 1]);
        }

        // ---- O += P @ V (V == K tile via trans ldsm), k-tile outer ----
        #pragma unroll
        for (int kt = 0; kt < 8; kt++) {
            const int brw = kt * 16 + ((lg & 1) << 3) + li;
            const int bcl = (lg >> 1) << 3;
            uint32_t bh[8][4];
            #pragma unroll
            for (int dp = 0; dp < 8; dp++)
                ldsm_x4t(bh[dp], KH + (brw * LDT + dp * 16 + bcl) * 2);
            #pragma unroll
            for (int dp = 0; dp < 8; dp++) {
                mma_bf16(o[2 * dp],     ph[kt], bh[dp]);
                mma_bf16(o[2 * dp + 1], ph[kt], bh[dp] + 2);
            }
            #pragma unroll
            for (int dp = 0; dp < 8; dp++) {
                mma_bf16(o[2 * dp],     pl[kt], bh[dp]);
                mma_bf16(o[2 * dp + 1], pl[kt], bh[dp] + 2);
            }
            #pragma unroll
            for (int dp = 0; dp < 8; dp++) {
                uint32_t bl[4];
                ldsm_x4t(bl, KL + (brw * LDT + dp * 16 + bcl) * 2);
                mma_bf16(o[2 * dp],     ph[kt], bl);
                mma_bf16(o[2 * dp + 1], ph[kt], bl + 2);
            }
        }

        CP_WAIT0();
        __syncthreads();
    }

    // ---- normalize, split to bf16 hi/lo, store itr planes ----
    lsum0 += __shfl_xor_sync(0xffffffffu, lsum0, 1);
    lsum0 += __shfl_xor_sync(0xffffffffu, lsum0, 2);
    lsum1 += __shfl_xor_sync(0xffffffffu, lsum1, 1);
    lsum1 += __shfl_xor_sync(0xffffffffu, lsum1, 2);
    float inv0 = 1.f / lsum0, inv1 = 1.f / lsum1;
    const size_t r0 = brow0 + i0 + wm * 16 + qr;
    #pragma unroll
    for (int dn = 0; dn < 16; dn++) {
        int cp = dn * 4 + (qc2 >> 1);           // u32 (pair) column index
        uint32_t h, l;
        split2(o[dn][0] * inv0, o[dn][1] * inv0, h, l);
        g_Ih[r0 * 64 + cp] = h;  g_Il[r0 * 64 + cp] = l;
        split2(o[dn][2] * inv1, o[dn][3] * inv1, h, l);
        g_Ih[(r0 + 8) * 64 + cp] = h;  g_Il[(r0 + 8) * 64 + cp] = l;
    }
}

// ===========================================================================
// HMMA fused gated MLP: X=[P,itr] (64 rows/CTA, K=256), all 3 gates in one
// k-pass (A-fragments reused x3), W streamed in k-chunks of 32 with cp.async
// double buffering. X copied from precomputed planes (no conversion).
// ===========================================================================
#define XLD 264
#define MXH 0
#define MXL 33792
#define MW0 67584             // per buf: 3 gates x [hi 8704 | lo 8704] = 52224
#define MW1 119808
#define MTOT 172032

__device__ __forceinline__ void copy_wchunk(uint32_t dst, int ch, int tid) {
    #pragma unroll
    for (int t = 0; t < 12; t++) {
        int idx = tid + t * 256;             // 3072 chunks
        int g = idx >> 10;
        int rem = idx & 1023;
        int lohi = rem >> 9;
        int rr = (rem >> 4) & 31;
        int c8 = rem & 15;
        const uint32_t* src = (lohi ? g_wlu : g_whu) + g * 16384 + (ch * 32 + rr) * 64 + c8 * 4;
        cpa16(dst + g * 17408 + lohi * 8704 + (uint32_t)(rr * LDT + c8 * 8) * 2, src);
    }
}

__global__ __launch_bounds__(256, 1)
void mlp_hmma(const float* __restrict__ P,
              const float* __restrict__ b1, const float* __restrict__ b2,
              const float* __restrict__ b3, float* __restrict__ out) {
    extern __shared__ char smem[];
    const uint32_t sb = smem_u32(smem);
    const int tid = threadIdx.x, lane = tid & 31, wid = tid >> 5;
    const int wm = wid & 3, wn = wid >> 2;
    const int lg = lane >> 3, li = lane & 7;
    const int qr = lane >> 2, qc2 = (lane & 3) << 1;
    const int row0 = blockIdx.x * 64;

    // preload X (copy planes) + W chunk 0
    #pragma unroll
    for (int t = 0; t < 8; t++) {
        int idx = tid + t * 256;             // 2048 chunks (64 rows x 32)
        int r = idx >> 5, c8 = idx & 31;
        int half = c8 >> 4, c8f = c8 & 15;
        const uint32_t* sH = (half ? g_Ih : g_Ph) + (size_t)(row0 + r) * 64 + c8f * 4;
        const uint32_t* sL = (half ? g_Il : g_Pl) + (size_t)(row0 + r) * 64 + c8f * 4;
        uint32_t doff = (uint32_t)(r * XLD + c8 * 8) * 2;
        cpa16(sb + MXH + doff, sH);
        cpa16(sb + MXL + doff, sL);
    }
    copy_wchunk(sb + MW0, 0, tid);
    CP_COMMIT();
    CP_WAIT0();
    __syncthreads();

    float acc[3][8][4];
    #pragma unroll
    for (int g = 0; g < 3; g++)
        #pragma unroll
        for (int n = 0; n < 8; n++)
            #pragma unroll
            for (int u = 0; u < 4; u++) acc[g][n][u] = 0.f;

    for (int ch = 0; ch < 8; ch++) {
        const int cur = ch & 1;
        const uint32_t wcur = sb + (cur ? MW1 : MW0);
        if (ch < 7) {
            copy_wchunk(sb + (cur ? MW0 : MW1), ch + 1, tid);
            CP_COMMIT();
        }

        #pragma unroll
        for (int ktc = 0; ktc < 2; ktc++) {
            const int arow = wm * 16 + ((lg & 1) << 3) + li;
            const int acol = (ch * 2 + ktc) * 16 + ((lg >> 1) << 3);
            uint32_t ah[4], al[4];
            ldsm_x4(ah, sb + MXH + (arow * XLD + acol) * 2);
            ldsm_x4(al, sb + MXL + (arow * XLD + acol) * 2);

            const int brw = ktc * 16 + ((lg & 1) << 3) + li;
            const int bcl = wn * 64 + ((lg >> 1) << 3);
            #pragma unroll
            for (int g = 0; g < 3; g++) {
                const uint32_t WH = wcur + g * 17408;
                const uint32_t WL = WH + 8704;
                uint32_t bh[4][4];
                #pragma unroll
                for (int np = 0; np < 4; np++)
                    ldsm_x4t(bh[np], WH + (brw * LDT + np * 16 + bcl) * 2);
                #pragma unroll
                for (int np = 0; np < 4; np++) {
                    mma_bf16(acc[g][2 * np],     ah, bh[np]);
                    mma_bf16(acc[g][2 * np + 1], ah, bh[np] + 2);
                }
                #pragma unroll
                for (int np = 0; np < 4; np++) {
                    mma_bf16(acc[g][2 * np],     al, bh[np]);
                    mma_bf16(acc[g][2 * np + 1], al, bh[np] + 2);
                }
                #pragma unroll
                for (int np = 0; np < 4; np++) {
                    uint32_t bl[4];
                    ldsm_x4t(bl, WL + (brw * LDT + np * 16 + bcl) * 2);
                    mma_bf16(acc[g][2 * np],     ah, bl);
                    mma_bf16(acc[g][2 * np + 1], ah, bl + 2);
                }
            }
        }

        CP_WAIT0();
        __syncthreads();
    }

    // ---- epilogue: out = sigmoid(a2+b2)*P + sigmoid(a3+b3)*tanh(a1+b1) ----
    #pragma unroll
    for (int n = 0; n < 8; n++) {
        int c = wn * 64 + n * 8 + qc2;
        float bb1x = b1[c], bb1y = b1[c + 1];
        float bb2x = b2[c], bb2y = b2[c + 1];
        float bb3x = b3[c], bb3y = b3[c + 1];
        #pragma unroll
        for (int half = 0; half < 2; half++) {
            size_t r = (size_t)row0 + wm * 16 + qr + half * 8;
            float2 pv = *(const float2*)(P + r * Dd + c);
            float a1x = acc[0][n][half * 2], a1y = acc[0][n][half * 2 + 1];
            float a2x = acc[1][n][half * 2], a2y = acc[1][n][half * 2 + 1];
            float a3x = acc[2][n][half * 2], a3y = acc[2][n][half * 2 + 1];
            float zx = tanhf(a1x + bb1x), zy = tanhf(a1y + bb1y);
            float rx = 1.f / (1.f + __expf(-(a2x + bb2x)));
            float ry = 1.f / (1.f + __expf(-(a2y + bb2y)));
            float fx = 1.f / (1.f + __expf(-(a3x + bb3x)));
            float fy = 1.f / (1.f + __expf(-(a3y + bb3y)));
            *(float2*)(out + r * Dd + c) =
                make_float2(rx * pv.x + fx * zx, ry * pv.y + fy * zy);
        }
    }
}

// ===========================================================================
extern "C" void kernel_launch(void* const* d_in, const int* in_sizes, int n_in,
                              void* d_out, int out_size) {
    const float* P  = (const float*)d_in[0];
    const float* w  = (const float*)d_in[1];
    const float* w1 = (const float*)d_in[2];
    const float* w2 = (const float*)d_in[3];
    const float* w3 = (const float*)d_in[4];
    const float* b1 = (const float*)d_in[5];
    const float* b2 = (const float*)d_in[6];
    const float* b3 = (const float*)d_in[7];
    float* out = (float*)d_out;

    cudaFuncSetAttribute(flash_hmma, cudaFuncAttributeMaxDynamicSharedMemorySize, FTOT);
    cudaFuncSetAttribute(mlp_hmma, cudaFuncAttributeMaxDynamicSharedMemorySize, MTOT);

    wsplit_kernel<<<64, 256>>>(w1, w2, w3);
    prep_kernel<<<NROWS / 8, 256>>>(P, w);

    dim3 fg(Nn / 128, Bsz);
    flash_hmma<<<fg, 256, FTOT>>>();

    mlp_hmma<<<NROWS / 64, 256, MTOT>>>(P, b1, b2, b3, out);
}

// round 9
// speedup vs baseline: 1.5034x; 1.0027x over previous
#include <cuda_runtime.h>
#include <cuda_bf16.h>
#include <cstdint>
#include <math.h>

#define Bsz 32
#define Nn  1024
#define Dd  128
#define NROWS (Bsz*Nn)

// Scratch (device globals: allocation-free rule). u32 = bf16x2 pairs.
__device__ float    g_qa[NROWS];             // qa[j] = P[j].wa
__device__ uint32_t g_Qh[NROWS * 64];        // (P*wc) hi  (flash Q plane)
__device__ uint32_t g_Ql[NROWS * 64];        // (P*wc) lo
__device__ uint32_t g_Ph[NROWS * 64];        // P hi       (flash K/V plane)
__device__ uint32_t g_Pl[NROWS * 64];        // P lo
// X = [P | itr] in A-fragment-major layout for mlp:
// index ((rb*16 + kb)*32 + lane)*8 : [0..3] = hi a0..a3, [4..7] = lo a0..a3
__device__ uint32_t g_Xf[(NROWS / 16) * 16 * 32 * 8];
// W in B-fragment-major layout: index (((g*16+kb)*16+nb)*32+lane)*4 :
// {w0 hi, w1 hi, w0 lo, w1 lo}
__device__ uint32_t g_Wf[3 * 16 * 16 * 32 * 4];

// ===========================================================================
// helpers
// ===========================================================================
__device__ __forceinline__ uint32_t smem_u32(const void* p) {
    uint32_t a;
    asm("{ .reg .u64 t; cvta.to.shared.u64 t, %1; cvt.u32.u64 %0, t; }" : "=r"(a) : "l"(p));
    return a;
}
__device__ __forceinline__ void ldsm_x4(uint32_t a[4], uint32_t addr) {
    asm volatile("ldmatrix.sync.aligned.m8n8.x4.shared.b16 {%0,%1,%2,%3}, [%4];"
        : "=r"(a[0]), "=r"(a[1]), "=r"(a[2]), "=r"(a[3]) : "r"(addr));
}
__device__ __forceinline__ void ldsm_x4t(uint32_t a[4], uint32_t addr) {
    asm volatile("ldmatrix.sync.aligned.m8n8.x4.trans.shared.b16 {%0,%1,%2,%3}, [%4];"
        : "=r"(a[0]), "=r"(a[1]), "=r"(a[2]), "=r"(a[3]) : "r"(addr));
}
__device__ __forceinline__ void mma_bf16(float c[4], const uint32_t a[4], const uint32_t b[2]) {
    asm volatile("mma.sync.aligned.m16n8k16.row.col.f32.bf16.bf16.f32 "
        "{%0,%1,%2,%3}, {%4,%5,%6,%7}, {%8,%9}, {%0,%1,%2,%3};"
        : "+f"(c[0]), "+f"(c[1]), "+f"(c[2]), "+f"(c[3])
        : "r"(a[0]), "r"(a[1]), "r"(a[2]), "r"(a[3]), "r"(b[0]), "r"(b[1]));
}
__device__ __forceinline__ void split2(float x, float y, uint32_t& h, uint32_t& l) {
    __nv_bfloat16 hx = __float2bfloat16_rn(x), hy = __float2bfloat16_rn(y);
    __nv_bfloat162 hv = __halves2bfloat162(hx, hy);
    h = *(uint32_t*)&hv;
    __nv_bfloat162 lv = __halves2bfloat162(
        __float2bfloat16_rn(x - __bfloat162float(hx)),
        __float2bfloat16_rn(y - __bfloat162float(hy)));
    l = *(uint32_t*)&lv;
}
__device__ __forceinline__ void cpa16(uint32_t dst, const void* src) {
    asm volatile("cp.async.cg.shared.global [%0], [%1], 16;" :: "r"(dst), "l"(src));
}
#define CP_COMMIT()  asm volatile("cp.async.commit_group;" ::: "memory")
#define CP_WAIT0()   asm volatile("cp.async.wait_group 0;" ::: "memory")

// ===========================================================================
// prep: per row -> qa dot, and bf16 hi/lo planes for P and Q=P*wc (flash use)
// ===========================================================================
__global__ void prep_kernel(const float* __restrict__ P, const float* __restrict__ w) {
    const int row  = blockIdx.x * 8 + (threadIdx.x >> 5);
    const int lane = threadIdx.x & 31;
    const float4 p  = *(const float4*)(P + (size_t)row * Dd + lane * 4);
    const float4 wa = *(const float4*)(w + lane * 4);
    const float4 wc = *(const float4*)(w + 2 * Dd + lane * 4);
    float s = p.x * wa.x + p.y * wa.y + p.z * wa.z + p.w * wa.w;
    #pragma unroll
    for (int off = 16; off > 0; off >>= 1) s += __shfl_xor_sync(0xffffffffu, s, off);
    if (lane == 0) g_qa[row] = s;
    const size_t o = (size_t)row * 64 + lane * 2;
    uint32_t h, l;
    split2(p.x, p.y, h, l);               g_Ph[o] = h;     g_Pl[o] = l;
    split2(p.z, p.w, h, l);               g_Ph[o + 1] = h; g_Pl[o + 1] = l;
    split2(p.x * wc.x, p.y * wc.y, h, l); g_Qh[o] = h;     g_Ql[o] = l;
    split2(p.z * wc.z, p.w * wc.w, h, l); g_Qh[o + 1] = h; g_Ql[o + 1] = l;
}

// X-fragment P part: block = row-block rb, warp = k-tile kb (0..7)
__global__ void xfrag_p_kernel(const float* __restrict__ P) {
    const int rb   = blockIdx.x;
    const int kb   = threadIdx.x >> 5;
    const int lane = threadIdx.x & 31;
    const int r0 = rb * 16 + (lane >> 2);
    const int c0 = kb * 16 + (lane & 3) * 2;
    const float* base = P + (size_t)r0 * Dd;
    float2 v00 = *(const float2*)(base + c0);
    float2 v10 = *(const float2*)(base + 8 * Dd + c0);
    float2 v01 = *(const float2*)(base + c0 + 8);
    float2 v11 = *(const float2*)(base + 8 * Dd + c0 + 8);
    uint32_t h0, l0, h1, l1, h2, l2, h3, l3;
    split2(v00.x, v00.y, h0, l0);
    split2(v10.x, v10.y, h1, l1);
    split2(v01.x, v01.y, h2, l2);
    split2(v11.x, v11.y, h3, l3);
    size_t off = (((size_t)rb * 16 + kb) * 32 + lane) * 8;
    *(uint4*)(g_Xf + off)     = make_uint4(h0, h1, h2, h3);
    *(uint4*)(g_Xf + off + 4) = make_uint4(l0, l1, l2, l3);
}

// W B-fragment-major split: idx = ((g*16+kb)*16+nb)*32+lane
__global__ void wsplit_frag(const float* __restrict__ w1, const float* __restrict__ w2,
                            const float* __restrict__ w3) {
    int idx = blockIdx.x * 256 + threadIdx.x;       // 24576 total
    if (idx >= 24576) return;
    int lane = idx & 31;
    int kb = (idx >> 9) & 15;
    int g  = idx >> 13;
    int nb = (idx >> 5) & 15;
    const float* W = (g == 0) ? w1 : (g == 1) ? w2 : w3;
    int k0 = kb * 16 + (lane & 3) * 2;
    int n  = nb * 8 + (lane >> 2);
    float x0 = W[k0 * 128 + n],       x1 = W[(k0 + 1) * 128 + n];
    float x2 = W[(k0 + 8) * 128 + n], x3 = W[(k0 + 9) * 128 + n];
    uint32_t h0, l0, h1, l1;
    split2(x0, x1, h0, l0);
    split2(x2, x3, h1, l1);
    *(uint4*)(g_Wf + (size_t)idx * 4) = make_uint4(h0, h1, l0, l1);
}

// ===========================================================================
// HMMA flash attention (BM=128, BN=128, 256 thr). Operand planes precomputed;
// K tiles double-buffered via cp.async. S = Qs @ Ks^T (+qa[j]); no-max
// softmax; probs in regs; K tile doubles as V via trans ldsm.
// Epilogue writes itr directly as mlp A-fragments (g_Xf kb 8..15).
// ===========================================================================
#define LDT 136
#define FQH  0
#define FQL  34816
#define FK0  69632            // [KH 34816 | KL 34816]
#define FK1  139264
#define FQA0 208896
#define FQA1 209408
#define FTOT 209920

__device__ __forceinline__ void copy_tile_pair(uint32_t dstHi, uint32_t dstLo,
        const uint32_t* __restrict__ srcHi, const uint32_t* __restrict__ srcLo,
        size_t grow0, int tid) {
    #pragma unroll
    for (int t = 0; t < 8; t++) {
        int idx = tid + t * 256;             // 2048 16B-chunks (128 rows x 16)
        int r = idx >> 4, c8 = idx & 15;
        uint32_t doff = (uint32_t)(r * LDT + c8 * 8) * 2;
        cpa16(dstHi + doff, srcHi + (grow0 + r) * 64 + c8 * 4);
        cpa16(dstLo + doff, srcLo + (grow0 + r) * 64 + c8 * 4);
    }
}

__global__ __launch_bounds__(256, 1)
void flash_hmma() {
    extern __shared__ char smem[];
    const uint32_t sb = smem_u32(smem);
    const int tid = threadIdx.x, lane = tid & 31, wm = tid >> 5;
    const int b = blockIdx.y, i0 = blockIdx.x * 128;
    const int lg = lane >> 3, li = lane & 7;
    const int qc2 = (lane & 3) << 1;
    const size_t brow0 = (size_t)b * Nn;

    copy_tile_pair(sb + FQH, sb + FQL, g_Qh, g_Ql, brow0 + i0, tid);
    copy_tile_pair(sb + FK0, sb + FK0 + 34816, g_Ph, g_Pl, brow0, tid);
    if (tid < 32) cpa16(sb + FQA0 + tid * 16, g_qa + brow0 + tid * 4);
    CP_COMMIT();
    CP_WAIT0();
    __syncthreads();

    float o[16][4];
    #pragma unroll
    for (int n = 0; n < 16; n++)
        #pragma unroll
        for (int u = 0; u < 4; u++) o[n][u] = 0.f;
    float lsum0 = 0.f, lsum1 = 0.f;

    for (int jt = 0; jt < 8; jt++) {
        const int cur = jt & 1;
        const uint32_t KH = sb + (cur ? FK1 : FK0);
        const uint32_t KL = KH + 34816;
        const float* qas = (const float*)(smem + (cur ? FQA1 : FQA0));

        if (jt < 7) {
            const uint32_t NKH = sb + (cur ? FK0 : FK1);
            copy_tile_pair(NKH, NKH + 34816, g_Ph, g_Pl, brow0 + (jt + 1) * 128, tid);
            if (tid < 32)
                cpa16(sb + (cur ? FQA0 : FQA1) + tid * 16, g_qa + brow0 + (jt + 1) * 128 + tid * 4);
            CP_COMMIT();
        }

        // ---- S = Q @ K^T, k-tile outer, terms QhKh + QlKh + QhKl ----
        float s[16][4];
        #pragma unroll
        for (int n = 0; n < 16; n++)
            #pragma unroll
            for (int u = 0; u < 4; u++) s[n][u] = 0.f;

        #pragma unroll
        for (int kt = 0; kt < 8; kt++) {
            const int arow = wm * 16 + ((lg & 1) << 3) + li;
            const int acol = kt * 16 + ((lg >> 1) << 3);
            uint32_t ah[4], al[4];
            ldsm_x4(ah, sb + FQH + (arow * LDT + acol) * 2);
            ldsm_x4(al, sb + FQL + (arow * LDT + acol) * 2);

            const int brw = ((lg >> 1) << 3) + li;
            const int bcl = kt * 16 + ((lg & 1) << 3);
            uint32_t bh[8][4];
            #pragma unroll
            for (int jp = 0; jp < 8; jp++)
                ldsm_x4(bh[jp], KH + ((jp * 16 + brw) * LDT + bcl) * 2);
            #pragma unroll
            for (int jp = 0; jp < 8; jp++) {
                mma_bf16(s[2 * jp],     ah, bh[jp]);
                mma_bf16(s[2 * jp + 1], ah, bh[jp] + 2);
            }
            #pragma unroll
            for (int jp = 0; jp < 8; jp++) {
                mma_bf16(s[2 * jp],     al, bh[jp]);
                mma_bf16(s[2 * jp + 1], al, bh[jp] + 2);
            }
            #pragma unroll
            for (int jp = 0; jp < 8; jp++) {
                uint32_t bl[4];
                ldsm_x4(bl, KL + ((jp * 16 + brw) * LDT + bcl) * 2);
                mma_bf16(s[2 * jp],     ah, bl);
                mma_bf16(s[2 * jp + 1], ah, bl + 2);
            }
        }

        // ---- exp (+qa col bias), pack probs into PV A-fragments ----
        uint32_t ph[8][4], pl[8][4];
        #pragma unroll
        for (int jn = 0; jn < 16; jn++) {
            int cb = jn * 8 + qc2;
            float q0 = qas[cb], q1 = qas[cb + 1];
            float p0 = __expf(s[jn][0] + q0);
            float p1 = __expf(s[jn][1] + q1);
            float p2 = __expf(s[jn][2] + q0);
            float p3 = __expf(s[jn][3] + q1);
            lsum0 += p0 + p1;
            lsum1 += p2 + p3;
            int kt = jn >> 1, hv = (jn & 1) << 1;
            split2(p0, p1, ph[kt][hv],     pl[kt][hv]);
            split2(p2, p3, ph[kt][hv + 1], pl[kt][hv + 1]);
        }

        // ---- O += P @ V (V == K tile via trans ldsm), k-tile outer ----
        #pragma unroll
        for (int kt = 0; kt < 8; kt++) {
            const int brw = kt * 16 + ((lg & 1) << 3) + li;
            const int bcl = (lg >> 1) << 3;
            uint32_t bh[8][4];
            #pragma unroll
            for (int dp = 0; dp < 8; dp++)
                ldsm_x4t(bh[dp], KH + (brw * LDT + dp * 16 + bcl) * 2);
            #pragma unroll
            for (int dp = 0; dp < 8; dp++) {
                mma_bf16(o[2 * dp],     ph[kt], bh[dp]);
                mma_bf16(o[2 * dp + 1], ph[kt], bh[dp] + 2);
            }
            #pragma unroll
            for (int dp = 0; dp < 8; dp++) {
                mma_bf16(o[2 * dp],     pl[kt], bh[dp]);
                mma_bf16(o[2 * dp + 1], pl[kt], bh[dp] + 2);
            }
            #pragma unroll
            for (int dp = 0; dp < 8; dp++) {
                uint32_t bl[4];
                ldsm_x4t(bl, KL + (brw * LDT + dp * 16 + bcl) * 2);
                mma_bf16(o[2 * dp],     ph[kt], bl);
                mma_bf16(o[2 * dp + 1], ph[kt], bl + 2);
            }
        }

        CP_WAIT0();
        __syncthreads();
    }

    // ---- normalize and emit itr as mlp A-fragments (g_Xf kb 8..15) ----
    lsum0 += __shfl_xor_sync(0xffffffffu, lsum0, 1);
    lsum0 += __shfl_xor_sync(0xffffffffu, lsum0, 2);
    lsum1 += __shfl_xor_sync(0xffffffffu, lsum1, 1);
    lsum1 += __shfl_xor_sync(0xffffffffu, lsum1, 2);
    float inv0 = 1.f / lsum0, inv1 = 1.f / lsum1;
    const size_t rbg = (brow0 + i0) / 16 + wm;
    #pragma unroll
    for (int kb = 0; kb < 8; kb++) {
        uint32_t h0, l0, h1, l1, h2, l2, h3, l3;
        split2(o[2 * kb][0] * inv0,     o[2 * kb][1] * inv0,     h0, l0);
        split2(o[2 * kb][2] * inv1,     o[2 * kb][3] * inv1,     h1, l1);
        split2(o[2 * kb + 1][0] * inv0, o[2 * kb + 1][1] * inv0, h2, l2);
        split2(o[2 * kb + 1][2] * inv1, o[2 * kb + 1][3] * inv1, h3, l3);
        size_t off = ((rbg * 16 + 8 + kb) * 32 + lane) * 8;
        *(uint4*)(g_Xf + off)     = make_uint4(h0, h1, h2, h3);
        *(uint4*)(g_Xf + off + 4) = make_uint4(l0, l1, l2, l3);
    }
}

// ===========================================================================
// Fragment-direct fused gated MLP: no smem, no barriers. 256 threads,
// 8 warps = 4 row-blocks x 2 n-halves; all fragments via LDG.128 from
// fragment-major globals. 3 gates x 8 n-frags x 3 split terms per k-tile.
// ===========================================================================
__global__ __launch_bounds__(256, 1)
void mlp_frag(const float* __restrict__ P,
              const float* __restrict__ b1, const float* __restrict__ b2,
              const float* __restrict__ b3, float* __restrict__ out) {
    const int tid = threadIdx.x, lane = tid & 31, wid = tid >> 5;
    const int rbl = wid & 3, wn = wid >> 2;
    const int qr = lane >> 2, qc2 = (lane & 3) << 1;
    const size_t rb = (size_t)blockIdx.x * 4 + rbl;

    float acc[3][8][4];
    #pragma unroll
    for (int g = 0; g < 3; g++)
        #pragma unroll
        for (int n = 0; n < 8; n++)
            #pragma unroll
            for (int u = 0; u < 4; u++) acc[g][n][u] = 0.f;

    #pragma unroll 4
    for (int kb = 0; kb < 16; kb++) {
        const uint32_t* xsrc = g_Xf + ((rb * 16 + kb) * 32 + lane) * 8;
        uint4 ahv = *(const uint4*)(xsrc);
        uint4 alv = *(const uint4*)(xsrc + 4);
        uint32_t ah[4] = { ahv.x, ahv.y, ahv.z, ahv.w };
        uint32_t al[4] = { alv.x, alv.y, alv.z, alv.w };

        #pragma unroll
        for (int g = 0; g < 3; g++) {
            uint4 wv[8];
            const uint32_t* wsrc = g_Wf + (size_t)(((g * 16 + kb) * 16 + wn * 8) * 32 + lane) * 4;
            #pragma unroll
            for (int nf = 0; nf < 8; nf++)
                wv[nf] = *(const uint4*)(wsrc + nf * 128);
            #pragma unroll
            for (int nf = 0; nf < 8; nf++) {
                uint32_t bh[2] = { wv[nf].x, wv[nf].y };
                mma_bf16(acc[g][nf], ah, bh);
            }
            #pragma unroll
            for (int nf = 0; nf < 8; nf++) {
                uint32_t bh[2] = { wv[nf].x, wv[nf].y };
                mma_bf16(acc[g][nf], al, bh);
            }
            #pragma unroll
            for (int nf = 0; nf < 8; nf++) {
                uint32_t bl[2] = { wv[nf].z, wv[nf].w };
                mma_bf16(acc[g][nf], ah, bl);
            }
        }
    }

    // ---- epilogue: out = sigmoid(a2+b2)*P + sigmoid(a3+b3)*tanh(a1+b1) ----
    #pragma unroll
    for (int n = 0; n < 8; n++) {
        int c = wn * 64 + n * 8 + qc2;
        float bb1x = b1[c], bb1y = b1[c + 1];
        float bb2x = b2[c], bb2y = b2[c + 1];
        float bb3x = b3[c], bb3y = b3[c + 1];
        #pragma unroll
        for (int half = 0; half < 2; half++) {
            size_t r = rb * 16 + qr + half * 8;
            float2 pv = *(const float2*)(P + r * Dd + c);
            float a1x = acc[0][n][half * 2], a1y = acc[0][n][half * 2 + 1];
            float a2x = acc[1][n][half * 2], a2y = acc[1][n][half * 2 + 1];
            float a3x = acc[2][n][half * 2], a3y = acc[2][n][half * 2 + 1];
            float zx = tanhf(a1x + bb1x), zy = tanhf(a1y + bb1y);
            float rx = 1.f / (1.f + __expf(-(a2x + bb2x)));
            float ry = 1.f / (1.f + __expf(-(a2y + bb2y)));
            float fx = 1.f / (1.f + __expf(-(a3x + bb3x)));
            float fy = 1.f / (1.f + __expf(-(a3y + bb3y)));
            *(float2*)(out + r * Dd + c) =
                make_float2(rx * pv.x + fx * zx, ry * pv.y + fy * zy);
        }
    }
}

// ===========================================================================
extern "C" void kernel_launch(void* const* d_in, const int* in_sizes, int n_in,
                              void* d_out, int out_size) {
    const float* P  = (const float*)d_in[0];
    const float* w  = (const float*)d_in[1];
    const float* w1 = (const float*)d_in[2];
    const float* w2 = (const float*)d_in[3];
    const float* w3 = (const float*)d_in[4];
    const float* b1 = (const float*)d_in[5];
    const float* b2 = (const float*)d_in[6];
    const float* b3 = (const float*)d_in[7];
    float* out = (float*)d_out;

    cudaFuncSetAttribute(flash_hmma, cudaFuncAttributeMaxDynamicSharedMemorySize, FTOT);

    wsplit_frag<<<96, 256>>>(w1, w2, w3);
    prep_kernel<<<NROWS / 8, 256>>>(P, w);
    xfrag_p_kernel<<<NROWS / 16, 256>>>(P);

    dim3 fg(Nn / 128, Bsz);
    flash_hmma<<<fg, 256, FTOT>>>();

    mlp_frag<<<NROWS / 64, 256>>>(P, b1, b2, b3, out);
}

// round 10
// speedup vs baseline: 1.8397x; 1.2237x over previous
#include <cuda_runtime.h>
#include <cuda_bf16.h>
#include <cstdint>
#include <math.h>

#define Bsz 32
#define Nn  1024
#define Dd  128
#define NROWS (Bsz*Nn)

// Scratch (device globals: allocation-free rule). u32 = bf16x2 pairs.
__device__ float    g_qa[NROWS];             // qa[j] = P[j].wa
__device__ uint32_t g_Qh[NROWS * 64];        // (P*wc) hi  (flash Q plane)
__device__ uint32_t g_Ql[NROWS * 64];        // (P*wc) lo
__device__ uint32_t g_Ph[NROWS * 64];        // P hi       (flash K/V plane)
__device__ uint32_t g_Pl[NROWS * 64];        // P lo
// X = [P | itr] in A-fragment-major layout for mlp:
// index ((rb*16 + kb)*32 + lane)*8 : [0..3] = hi a0..a3, [4..7] = lo a0..a3
__device__ uint32_t g_Xf[(NROWS / 16) * 16 * 32 * 8];
// W in B-fragment-major layout: index (((g*16+kb)*16+nb)*32+lane)*4 :
// {w0 hi, w1 hi, w0 lo, w1 lo}
__device__ uint32_t g_Wf[3 * 16 * 16 * 32 * 4];

// ===========================================================================
// helpers
// ===========================================================================
__device__ __forceinline__ uint32_t smem_u32(const void* p) {
    uint32_t a;
    asm("{ .reg .u64 t; cvta.to.shared.u64 t, %1; cvt.u32.u64 %0, t; }" : "=r"(a) : "l"(p));
    return a;
}
__device__ __forceinline__ void ldsm_x4(uint32_t a[4], uint32_t addr) {
    asm volatile("ldmatrix.sync.aligned.m8n8.x4.shared.b16 {%0,%1,%2,%3}, [%4];"
        : "=r"(a[0]), "=r"(a[1]), "=r"(a[2]), "=r"(a[3]) : "r"(addr));
}
__device__ __forceinline__ void ldsm_x4t(uint32_t a[4], uint32_t addr) {
    asm volatile("ldmatrix.sync.aligned.m8n8.x4.trans.shared.b16 {%0,%1,%2,%3}, [%4];"
        : "=r"(a[0]), "=r"(a[1]), "=r"(a[2]), "=r"(a[3]) : "r"(addr));
}
__device__ __forceinline__ void mma_bf16(float c[4], const uint32_t a[4], const uint32_t b[2]) {
    asm volatile("mma.sync.aligned.m16n8k16.row.col.f32.bf16.bf16.f32 "
        "{%0,%1,%2,%3}, {%4,%5,%6,%7}, {%8,%9}, {%0,%1,%2,%3};"
        : "+f"(c[0]), "+f"(c[1]), "+f"(c[2]), "+f"(c[3])
        : "r"(a[0]), "r"(a[1]), "r"(a[2]), "r"(a[3]), "r"(b[0]), "r"(b[1]));
}
__device__ __forceinline__ void split2(float x, float y, uint32_t& h, uint32_t& l) {
    __nv_bfloat16 hx = __float2bfloat16_rn(x), hy = __float2bfloat16_rn(y);
    __nv_bfloat162 hv = __halves2bfloat162(hx, hy);
    h = *(uint32_t*)&hv;
    __nv_bfloat162 lv = __halves2bfloat162(
        __float2bfloat16_rn(x - __bfloat162float(hx)),
        __float2bfloat16_rn(y - __bfloat162float(hy)));
    l = *(uint32_t*)&lv;
}
// pack (lo,hi) floats -> bf16x2 in one cvt (first src -> HIGH half)
__device__ __forceinline__ uint32_t cvt2(float hi, float lo) {
    uint32_t d;
    asm("cvt.rn.bf16x2.f32 %0, %1, %2;" : "=r"(d) : "f"(hi), "f"(lo));
    return d;
}
__device__ __forceinline__ void cpa16(uint32_t dst, const void* src) {
    asm volatile("cp.async.cg.shared.global [%0], [%1], 16;" :: "r"(dst), "l"(src));
}
#define CP_COMMIT()  asm volatile("cp.async.commit_group;" ::: "memory")
#define CP_WAIT0()   asm volatile("cp.async.wait_group 0;" ::: "memory")

// ===========================================================================
// prep: per row -> qa dot, and bf16 hi/lo planes for P and Q=P*wc (flash use)
// ===========================================================================
__global__ void prep_kernel(const float* __restrict__ P, const float* __restrict__ w) {
    const int row  = blockIdx.x * 8 + (threadIdx.x >> 5);
    const int lane = threadIdx.x & 31;
    const float4 p  = *(const float4*)(P + (size_t)row * Dd + lane * 4);
    const float4 wa = *(const float4*)(w + lane * 4);
    const float4 wc = *(const float4*)(w + 2 * Dd + lane * 4);
    float s = p.x * wa.x + p.y * wa.y + p.z * wa.z + p.w * wa.w;
    #pragma unroll
    for (int off = 16; off > 0; off >>= 1) s += __shfl_xor_sync(0xffffffffu, s, off);
    if (lane == 0) g_qa[row] = s;
    const size_t o = (size_t)row * 64 + lane * 2;
    uint32_t h, l;
    split2(p.x, p.y, h, l);               g_Ph[o] = h;     g_Pl[o] = l;
    split2(p.z, p.w, h, l);               g_Ph[o + 1] = h; g_Pl[o + 1] = l;
    split2(p.x * wc.x, p.y * wc.y, h, l); g_Qh[o] = h;     g_Ql[o] = l;
    split2(p.z * wc.z, p.w * wc.w, h, l); g_Qh[o + 1] = h; g_Ql[o + 1] = l;
}

// X-fragment P part: block = row-block rb, warp = k-tile kb (0..7)
__global__ void xfrag_p_kernel(const float* __restrict__ P) {
    const int rb   = blockIdx.x;
    const int kb   = threadIdx.x >> 5;
    const int lane = threadIdx.x & 31;
    const int r0 = rb * 16 + (lane >> 2);
    const int c0 = kb * 16 + (lane & 3) * 2;
    const float* base = P + (size_t)r0 * Dd;
    float2 v00 = *(const float2*)(base + c0);
    float2 v10 = *(const float2*)(base + 8 * Dd + c0);
    float2 v01 = *(const float2*)(base + c0 + 8);
    float2 v11 = *(const float2*)(base + 8 * Dd + c0 + 8);
    uint32_t h0, l0, h1, l1, h2, l2, h3, l3;
    split2(v00.x, v00.y, h0, l0);
    split2(v10.x, v10.y, h1, l1);
    split2(v01.x, v01.y, h2, l2);
    split2(v11.x, v11.y, h3, l3);
    size_t off = (((size_t)rb * 16 + kb) * 32 + lane) * 8;
    *(uint4*)(g_Xf + off)     = make_uint4(h0, h1, h2, h3);
    *(uint4*)(g_Xf + off + 4) = make_uint4(l0, l1, l2, l3);
}

// W B-fragment-major split: idx = ((g*16+kb)*16+nb)*32+lane
__global__ void wsplit_frag(const float* __restrict__ w1, const float* __restrict__ w2,
                            const float* __restrict__ w3) {
    int idx = blockIdx.x * 256 + threadIdx.x;       // 24576 total
    if (idx >= 24576) return;
    int lane = idx & 31;
    int kb = (idx >> 9) & 15;
    int g  = idx >> 13;
    int nb = (idx >> 5) & 15;
    const float* W = (g == 0) ? w1 : (g == 1) ? w2 : w3;
    int k0 = kb * 16 + (lane & 3) * 2;
    int n  = nb * 8 + (lane >> 2);
    float x0 = W[k0 * 128 + n],       x1 = W[(k0 + 1) * 128 + n];
    float x2 = W[(k0 + 8) * 128 + n], x3 = W[(k0 + 9) * 128 + n];
    uint32_t h0, l0, h1, l1;
    split2(x0, x1, h0, l0);
    split2(x2, x3, h1, l1);
    *(uint4*)(g_Wf + (size_t)idx * 4) = make_uint4(h0, h1, l0, l1);
}

// ===========================================================================
// HMMA flash attention (BM=128, BN=128, 256 thr). Operand planes precomputed;
// K tiles double-buffered via cp.async. S = 3-term bf16 split; PV = 1-term
// pure-bf16 (prob+V quantization errors are random-sign weighted averages;
// itr rel err ~1e-4, damped further through the 0.05-scale MLP gates).
// Epilogue writes itr directly as mlp A-fragments (g_Xf kb 8..15).
// ===========================================================================
#define LDT 136
#define FQH  0
#define FQL  34816
#define FK0  69632            // [KH 34816 | KL 34816]
#define FK1  139264
#define FQA0 208896
#define FQA1 209408
#define FTOT 209920

__device__ __forceinline__ void copy_tile_pair(uint32_t dstHi, uint32_t dstLo,
        const uint32_t* __restrict__ srcHi, const uint32_t* __restrict__ srcLo,
        size_t grow0, int tid) {
    #pragma unroll
    for (int t = 0; t < 8; t++) {
        int idx = tid + t * 256;             // 2048 16B-chunks (128 rows x 16)
        int r = idx >> 4, c8 = idx & 15;
        uint32_t doff = (uint32_t)(r * LDT + c8 * 8) * 2;
        cpa16(dstHi + doff, srcHi + (grow0 + r) * 64 + c8 * 4);
        cpa16(dstLo + doff, srcLo + (grow0 + r) * 64 + c8 * 4);
    }
}

__global__ __launch_bounds__(256, 1)
void flash_hmma() {
    extern __shared__ char smem[];
    const uint32_t sb = smem_u32(smem);
    const int tid = threadIdx.x, lane = tid & 31, wm = tid >> 5;
    const int b = blockIdx.y, i0 = blockIdx.x * 128;
    const int lg = lane >> 3, li = lane & 7;
    const int qc2 = (lane & 3) << 1;
    const size_t brow0 = (size_t)b * Nn;

    copy_tile_pair(sb + FQH, sb + FQL, g_Qh, g_Ql, brow0 + i0, tid);
    copy_tile_pair(sb + FK0, sb + FK0 + 34816, g_Ph, g_Pl, brow0, tid);
    if (tid < 32) cpa16(sb + FQA0 + tid * 16, g_qa + brow0 + tid * 4);
    CP_COMMIT();
    CP_WAIT0();
    __syncthreads();

    float o[16][4];
    #pragma unroll
    for (int n = 0; n < 16; n++)
        #pragma unroll
        for (int u = 0; u < 4; u++) o[n][u] = 0.f;
    float lsum0 = 0.f, lsum1 = 0.f;

    for (int jt = 0; jt < 8; jt++) {
        const int cur = jt & 1;
        const uint32_t KH = sb + (cur ? FK1 : FK0);
        const uint32_t KL = KH + 34816;
        const float* qas = (const float*)(smem + (cur ? FQA1 : FQA0));

        if (jt < 7) {
            const uint32_t NKH = sb + (cur ? FK0 : FK1);
            copy_tile_pair(NKH, NKH + 34816, g_Ph, g_Pl, brow0 + (jt + 1) * 128, tid);
            if (tid < 32)
                cpa16(sb + (cur ? FQA0 : FQA1) + tid * 16, g_qa + brow0 + (jt + 1) * 128 + tid * 4);
            CP_COMMIT();
        }

        // ---- S = Q @ K^T, k-tile outer, terms QhKh + QlKh + QhKl ----
        float s[16][4];
        #pragma unroll
        for (int n = 0; n < 16; n++)
            #pragma unroll
            for (int u = 0; u < 4; u++) s[n][u] = 0.f;

        #pragma unroll
        for (int kt = 0; kt < 8; kt++) {
            const int arow = wm * 16 + ((lg & 1) << 3) + li;
            const int acol = kt * 16 + ((lg >> 1) << 3);
            uint32_t ah[4], al[4];
            ldsm_x4(ah, sb + FQH + (arow * LDT + acol) * 2);
            ldsm_x4(al, sb + FQL + (arow * LDT + acol) * 2);

            const int brw = ((lg >> 1) << 3) + li;
            const int bcl = kt * 16 + ((lg & 1) << 3);
            uint32_t bh[8][4];
            #pragma unroll
            for (int jp = 0; jp < 8; jp++)
                ldsm_x4(bh[jp], KH + ((jp * 16 + brw) * LDT + bcl) * 2);
            #pragma unroll
            for (int jp = 0; jp < 8; jp++) {
                mma_bf16(s[2 * jp],     ah, bh[jp]);
                mma_bf16(s[2 * jp + 1], ah, bh[jp] + 2);
            }
            #pragma unroll
            for (int jp = 0; jp < 8; jp++) {
                mma_bf16(s[2 * jp],     al, bh[jp]);
                mma_bf16(s[2 * jp + 1], al, bh[jp] + 2);
            }
            #pragma unroll
            for (int jp = 0; jp < 8; jp++) {
                uint32_t bl[4];
                ldsm_x4(bl, KL + ((jp * 16 + brw) * LDT + bcl) * 2);
                mma_bf16(s[2 * jp],     ah, bl);
                mma_bf16(s[2 * jp + 1], ah, bl + 2);
            }
        }

        // ---- exp (+qa col bias), pack probs (bf16, 1-term PV) ----
        uint32_t ph[8][4];
        #pragma unroll
        for (int jn = 0; jn < 16; jn++) {
            int cb = jn * 8 + qc2;
            float q0 = qas[cb], q1 = qas[cb + 1];
            float p0 = __expf(s[jn][0] + q0);
            float p1 = __expf(s[jn][1] + q1);
            float p2 = __expf(s[jn][2] + q0);
            float p3 = __expf(s[jn][3] + q1);
            lsum0 += p0 + p1;
            lsum1 += p2 + p3;
            int kt = jn >> 1, hv = (jn & 1) << 1;
            ph[kt][hv]     = cvt2(p1, p0);
            ph[kt][hv + 1] = cvt2(p3, p2);
        }

        // ---- O += P @ V (1-term: ph x Vh; V == K tile via trans ldsm) ----
        #pragma unroll
        for (int kt = 0; kt < 8; kt++) {
            const int brw = kt * 16 + ((lg & 1) << 3) + li;
            const int bcl = (lg >> 1) << 3;
            uint32_t bh[8][4];
            #pragma unroll
            for (int dp = 0; dp < 8; dp++)
                ldsm_x4t(bh[dp], KH + (brw * LDT + dp * 16 + bcl) * 2);
            #pragma unroll
            for (int dp = 0; dp < 8; dp++) {
                mma_bf16(o[2 * dp],     ph[kt], bh[dp]);
                mma_bf16(o[2 * dp + 1], ph[kt], bh[dp] + 2);
            }
        }

        CP_WAIT0();
        __syncthreads();
    }

    // ---- normalize and emit itr as mlp A-fragments (g_Xf kb 8..15) ----
    lsum0 += __shfl_xor_sync(0xffffffffu, lsum0, 1);
    lsum0 += __shfl_xor_sync(0xffffffffu, lsum0, 2);
    lsum1 += __shfl_xor_sync(0xffffffffu, lsum1, 1);
    lsum1 += __shfl_xor_sync(0xffffffffu, lsum1, 2);
    float inv0 = 1.f / lsum0, inv1 = 1.f / lsum1;
    const size_t rbg = (brow0 + i0) / 16 + wm;
    #pragma unroll
    for (int kb = 0; kb < 8; kb++) {
        uint32_t h0, l0, h1, l1, h2, l2, h3, l3;
        split2(o[2 * kb][0] * inv0,     o[2 * kb][1] * inv0,     h0, l0);
        split2(o[2 * kb][2] * inv1,     o[2 * kb][3] * inv1,     h1, l1);
        split2(o[2 * kb + 1][0] * inv0, o[2 * kb + 1][1] * inv0, h2, l2);
        split2(o[2 * kb + 1][2] * inv1, o[2 * kb + 1][3] * inv1, h3, l3);
        size_t off = ((rbg * 16 + 8 + kb) * 32 + lane) * 8;
        *(uint4*)(g_Xf + off)     = make_uint4(h0, h1, h2, h3);
        *(uint4*)(g_Xf + off + 4) = make_uint4(l0, l1, l2, l3);
    }
}

// ===========================================================================
// Fragment-direct fused gated MLP: no smem, no barriers. 256 threads,
// 8 warps = 4 row-blocks x 2 n-halves. Software-pipelined: W and A fragment
// register double-buffers, loads for block i+1 issued before mmas of block i.
// ===========================================================================
__global__ __launch_bounds__(256, 1)
void mlp_frag(const float* __restrict__ P,
              const float* __restrict__ b1, const float* __restrict__ b2,
              const float* __restrict__ b3, float* __restrict__ out) {
    const int tid = threadIdx.x, lane = tid & 31, wid = tid >> 5;
    const int rbl = wid & 3, wn = wid >> 2;
    const int qr = lane >> 2, qc2 = (lane & 3) << 1;
    const size_t rb = (size_t)blockIdx.x * 4 + rbl;

    const uint32_t* wb0 = g_Wf + (size_t)wn * 1024 + lane * 4;   // + g*32768 + kb*2048 + nf*128
    const uint32_t* xb0 = g_Xf + (rb * 16 * 32 + lane) * 8;      // + kb*256

    float acc[3][8][4];
    #pragma unroll
    for (int g = 0; g < 3; g++)
        #pragma unroll
        for (int n = 0; n < 8; n++)
            #pragma unroll
            for (int u = 0; u < 4; u++) acc[g][n][u] = 0.f;

    uint4 wv[2][8];
    uint4 av[2][2];

    // prologue: A(kb=0), W(blk=0)
    av[0][0] = *(const uint4*)(xb0);
    av[0][1] = *(const uint4*)(xb0 + 4);
    #pragma unroll
    for (int nf = 0; nf < 8; nf++)
        wv[0][nf] = *(const uint4*)(wb0 + nf * 128);

    #pragma unroll
    for (int blk = 0; blk < 48; blk++) {
        const int kb = blk / 3, g = blk - 3 * kb;
        // prefetch A for kb+1 at the start of each kb
        if (g == 0 && kb < 15) {
            const uint32_t* xs = xb0 + (kb + 1) * 256;
            av[(kb + 1) & 1][0] = *(const uint4*)(xs);
            av[(kb + 1) & 1][1] = *(const uint4*)(xs + 4);
        }
        // prefetch W for blk+1
        if (blk < 47) {
            const int nkb = (blk + 1) / 3, ng = (blk + 1) - 3 * nkb;
            const uint32_t* ws = wb0 + (size_t)ng * 32768 + nkb * 2048;
            #pragma unroll
            for (int nf = 0; nf < 8; nf++)
                wv[(blk + 1) & 1][nf] = *(const uint4*)(ws + nf * 128);
        }
        const uint32_t* ah = (const uint32_t*)&av[kb & 1][0];
        const uint32_t* al = (const uint32_t*)&av[kb & 1][1];
        const uint4* wc = wv[blk & 1];
        #pragma unroll
        for (int nf = 0; nf < 8; nf++) {
            uint32_t bh[2] = { wc[nf].x, wc[nf].y };
            mma_bf16(acc[g][nf], ah, bh);
        }
        #pragma unroll
        for (int nf = 0; nf < 8; nf++) {
            uint32_t bh[2] = { wc[nf].x, wc[nf].y };
            mma_bf16(acc[g][nf], al, bh);
        }
        #pragma unroll
        for (int nf = 0; nf < 8; nf++) {
            uint32_t bl[2] = { wc[nf].z, wc[nf].w };
            mma_bf16(acc[g][nf], ah, bl);
        }
    }

    // ---- epilogue: out = sigmoid(a2+b2)*P + sigmoid(a3+b3)*tanh(a1+b1) ----
    #pragma unroll
    for (int n = 0; n < 8; n++) {
        int c = wn * 64 + n * 8 + qc2;
        float bb1x = b1[c], bb1y = b1[c + 1];
        float bb2x = b2[c], bb2y = b2[c + 1];
        float bb3x = b3[c], bb3y = b3[c + 1];
        #pragma unroll
        for (int half = 0; half < 2; half++) {
            size_t r = rb * 16 + qr + half * 8;
            float2 pv = *(const float2*)(P + r * Dd + c);
            float a1x = acc[0][n][half * 2], a1y = acc[0][n][half * 2 + 1];
            float a2x = acc[1][n][half * 2], a2y = acc[1][n][half * 2 + 1];
            float a3x = acc[2][n][half * 2], a3y = acc[2][n][half * 2 + 1];
            float zx = tanhf(a1x + bb1x), zy = tanhf(a1y + bb1y);
            float rx = 1.f / (1.f + __expf(-(a2x + bb2x)));
            float ry = 1.f / (1.f + __expf(-(a2y + bb2y)));
            float fx = 1.f / (1.f + __expf(-(a3x + bb3x)));
            float fy = 1.f / (1.f + __expf(-(a3y + bb3y)));
            *(float2*)(out + r * Dd + c) =
                make_float2(rx * pv.x + fx * zx, ry * pv.y + fy * zy);
        }
    }
}

// ===========================================================================
extern "C" void kernel_launch(void* const* d_in, const int* in_sizes, int n_in,
                              void* d_out, int out_size) {
    const float* P  = (const float*)d_in[0];
    const float* w  = (const float*)d_in[1];
    const float* w1 = (const float*)d_in[2];
    const float* w2 = (const float*)d_in[3];
    const float* w3 = (const float*)d_in[4];
    const float* b1 = (const float*)d_in[5];
    const float* b2 = (const float*)d_in[6];
    const float* b3 = (const float*)d_in[7];
    float* out = (float*)d_out;

    cudaFuncSetAttribute(flash_hmma, cudaFuncAttributeMaxDynamicSharedMemorySize, FTOT);

    wsplit_frag<<<96, 256>>>(w1, w2, w3);
    prep_kernel<<<NROWS / 8, 256>>>(P, w);
    xfrag_p_kernel<<<NROWS / 16, 256>>>(P);

    dim3 fg(Nn / 128, Bsz);
    flash_hmma<<<fg, 256, FTOT>>>();

    mlp_frag<<<NROWS / 64, 256>>>(P, b1, b2, b3, out);
}

// round 11
// speedup vs baseline: 2.0956x; 1.1391x over previous
#include <cuda_runtime.h>
#include <cuda_bf16.h>
#include <cstdint>
#include <math.h>

#define Bsz 32
#define Nn  1024
#define Dd  128
#define NROWS (Bsz*Nn)

// Scratch (device globals: allocation-free rule). u32 = bf16x2 pairs.
__device__ float    g_qa[NROWS];             // qa[j] = P[j].wa
__device__ uint32_t g_Qh[NROWS * 64];        // (P*wc) hi  (flash Q plane)
__device__ uint32_t g_Ql[NROWS * 64];        // (P*wc) lo
__device__ uint32_t g_Ph[NROWS * 64];        // P hi       (flash K/V plane)
// X = [P | itr] in A-fragment-major layout for mlp:
// index ((rb*16 + kb)*32 + lane)*8 : [0..3] = hi a0..a3, [4..7] = lo a0..a3
__device__ uint32_t g_Xf[(NROWS / 16) * 16 * 32 * 8];
// W in B-fragment-major layout: index (((g*16+kb)*16+nb)*32+lane)*4 :
// {w0 hi, w1 hi, w0 lo, w1 lo}
__device__ uint32_t g_Wf[3 * 16 * 16 * 32 * 4];

// ===========================================================================
// helpers
// ===========================================================================
__device__ __forceinline__ uint32_t smem_u32(const void* p) {
    uint32_t a;
    asm("{ .reg .u64 t; cvta.to.shared.u64 t, %1; cvt.u32.u64 %0, t; }" : "=r"(a) : "l"(p));
    return a;
}
__device__ __forceinline__ void ldsm_x4(uint32_t a[4], uint32_t addr) {
    asm volatile("ldmatrix.sync.aligned.m8n8.x4.shared.b16 {%0,%1,%2,%3}, [%4];"
        : "=r"(a[0]), "=r"(a[1]), "=r"(a[2]), "=r"(a[3]) : "r"(addr));
}
__device__ __forceinline__ void ldsm_x4t(uint32_t a[4], uint32_t addr) {
    asm volatile("ldmatrix.sync.aligned.m8n8.x4.trans.shared.b16 {%0,%1,%2,%3}, [%4];"
        : "=r"(a[0]), "=r"(a[1]), "=r"(a[2]), "=r"(a[3]) : "r"(addr));
}
__device__ __forceinline__ void mma_bf16(float c[4], const uint32_t a[4], const uint32_t b[2]) {
    asm volatile("mma.sync.aligned.m16n8k16.row.col.f32.bf16.bf16.f32 "
        "{%0,%1,%2,%3}, {%4,%5,%6,%7}, {%8,%9}, {%0,%1,%2,%3};"
        : "+f"(c[0]), "+f"(c[1]), "+f"(c[2]), "+f"(c[3])
        : "r"(a[0]), "r"(a[1]), "r"(a[2]), "r"(a[3]), "r"(b[0]), "r"(b[1]));
}
__device__ __forceinline__ void split2(float x, float y, uint32_t& h, uint32_t& l) {
    __nv_bfloat16 hx = __float2bfloat16_rn(x), hy = __float2bfloat16_rn(y);
    __nv_bfloat162 hv = __halves2bfloat162(hx, hy);
    h = *(uint32_t*)&hv;
    __nv_bfloat162 lv = __halves2bfloat162(
        __float2bfloat16_rn(x - __bfloat162float(hx)),
        __float2bfloat16_rn(y - __bfloat162float(hy)));
    l = *(uint32_t*)&lv;
}
// pack (lo,hi) floats -> bf16x2 in one cvt (first src -> HIGH half)
__device__ __forceinline__ uint32_t cvt2(float hi, float lo) {
    uint32_t d;
    asm("cvt.rn.bf16x2.f32 %0, %1, %2;" : "=r"(d) : "f"(hi), "f"(lo));
    return d;
}
__device__ __forceinline__ void cpa16(uint32_t dst, const void* src) {
    asm volatile("cp.async.cg.shared.global [%0], [%1], 16;" :: "r"(dst), "l"(src));
}
#define CP_COMMIT()  asm volatile("cp.async.commit_group;" ::: "memory")
#define CP_WAIT0()   asm volatile("cp.async.wait_group 0;" ::: "memory")

// ===========================================================================
// prep: per row -> qa dot, and bf16 planes: Ph (K/V), Qh/Ql (Q = P*wc)
// ===========================================================================
__global__ void prep_kernel(const float* __restrict__ P, const float* __restrict__ w) {
    const int row  = blockIdx.x * 8 + (threadIdx.x >> 5);
    const int lane = threadIdx.x & 31;
    const float4 p  = *(const float4*)(P + (size_t)row * Dd + lane * 4);
    const float4 wa = *(const float4*)(w + lane * 4);
    const float4 wc = *(const float4*)(w + 2 * Dd + lane * 4);
    float s = p.x * wa.x + p.y * wa.y + p.z * wa.z + p.w * wa.w;
    #pragma unroll
    for (int off = 16; off > 0; off >>= 1) s += __shfl_xor_sync(0xffffffffu, s, off);
    if (lane == 0) g_qa[row] = s;
    const size_t o = (size_t)row * 64 + lane * 2;
    uint32_t h, l;
    g_Ph[o]     = cvt2(p.y, p.x);
    g_Ph[o + 1] = cvt2(p.w, p.z);
    split2(p.x * wc.x, p.y * wc.y, h, l); g_Qh[o] = h;     g_Ql[o] = l;
    split2(p.z * wc.z, p.w * wc.w, h, l); g_Qh[o + 1] = h; g_Ql[o + 1] = l;
}

// X-fragment P part: block = row-block rb, warp = k-tile kb (0..7)
__global__ void xfrag_p_kernel(const float* __restrict__ P) {
    const int rb   = blockIdx.x;
    const int kb   = threadIdx.x >> 5;
    const int lane = threadIdx.x & 31;
    const int r0 = rb * 16 + (lane >> 2);
    const int c0 = kb * 16 + (lane & 3) * 2;
    const float* base = P + (size_t)r0 * Dd;
    float2 v00 = *(const float2*)(base + c0);
    float2 v10 = *(const float2*)(base + 8 * Dd + c0);
    float2 v01 = *(const float2*)(base + c0 + 8);
    float2 v11 = *(const float2*)(base + 8 * Dd + c0 + 8);
    uint32_t h0, l0, h1, l1, h2, l2, h3, l3;
    split2(v00.x, v00.y, h0, l0);
    split2(v10.x, v10.y, h1, l1);
    split2(v01.x, v01.y, h2, l2);
    split2(v11.x, v11.y, h3, l3);
    size_t off = (((size_t)rb * 16 + kb) * 32 + lane) * 8;
    *(uint4*)(g_Xf + off)     = make_uint4(h0, h1, h2, h3);
    *(uint4*)(g_Xf + off + 4) = make_uint4(l0, l1, l2, l3);
}

// W B-fragment-major split: idx = ((g*16+kb)*16+nb)*32+lane
__global__ void wsplit_frag(const float* __restrict__ w1, const float* __restrict__ w2,
                            const float* __restrict__ w3) {
    int idx = blockIdx.x * 256 + threadIdx.x;       // 24576 total
    if (idx >= 24576) return;
    int lane = idx & 31;
    int kb = (idx >> 9) & 15;
    int g  = idx >> 13;
    int nb = (idx >> 5) & 15;
    const float* W = (g == 0) ? w1 : (g == 1) ? w2 : w3;
    int k0 = kb * 16 + (lane & 3) * 2;
    int n  = nb * 8 + (lane >> 2);
    float x0 = W[k0 * 128 + n],       x1 = W[(k0 + 1) * 128 + n];
    float x2 = W[(k0 + 8) * 128 + n], x3 = W[(k0 + 9) * 128 + n];
    uint32_t h0, l0, h1, l1;
    split2(x0, x1, h0, l0);
    split2(x2, x3, h1, l1);
    *(uint4*)(g_Wf + (size_t)idx * 4) = make_uint4(h0, h1, l0, l1);
}

// ===========================================================================
// HMMA flash attention (BM=128, BN=128, 256 thr). Operand planes precomputed;
// K tiles (single hi-plane) double-buffered via cp.async.
// S = (Qh+Ql) @ Kh^T (2-term split: K-residual term dropped — logit error
// ~1e-3 random-sign, averages out through softmax+PV). PV = 1-term bf16.
// Epilogue writes itr directly as mlp A-fragments (g_Xf kb 8..15).
// ===========================================================================
#define LDT 136
#define FQH  0
#define FQL  34816
#define FK0  69632            // KH only (34816)
#define FK1  104448
#define FQA0 139264
#define FQA1 139776
#define FTOT 140288

__device__ __forceinline__ void copy_tile_pair(uint32_t dstHi, uint32_t dstLo,
        const uint32_t* __restrict__ srcHi, const uint32_t* __restrict__ srcLo,
        size_t grow0, int tid) {
    #pragma unroll
    for (int t = 0; t < 8; t++) {
        int idx = tid + t * 256;             // 2048 16B-chunks (128 rows x 16)
        int r = idx >> 4, c8 = idx & 15;
        uint32_t doff = (uint32_t)(r * LDT + c8 * 8) * 2;
        cpa16(dstHi + doff, srcHi + (grow0 + r) * 64 + c8 * 4);
        cpa16(dstLo + doff, srcLo + (grow0 + r) * 64 + c8 * 4);
    }
}
__device__ __forceinline__ void copy_tile(uint32_t dst,
        const uint32_t* __restrict__ src, size_t grow0, int tid) {
    #pragma unroll
    for (int t = 0; t < 8; t++) {
        int idx = tid + t * 256;
        int r = idx >> 4, c8 = idx & 15;
        cpa16(dst + (uint32_t)(r * LDT + c8 * 8) * 2, src + (grow0 + r) * 64 + c8 * 4);
    }
}

__global__ __launch_bounds__(256, 1)
void flash_hmma() {
    extern __shared__ char smem[];
    const uint32_t sb = smem_u32(smem);
    const int tid = threadIdx.x, lane = tid & 31, wm = tid >> 5;
    const int b = blockIdx.y, i0 = blockIdx.x * 128;
    const int lg = lane >> 3, li = lane & 7;
    const int qc2 = (lane & 3) << 1;
    const size_t brow0 = (size_t)b * Nn;

    copy_tile_pair(sb + FQH, sb + FQL, g_Qh, g_Ql, brow0 + i0, tid);
    copy_tile(sb + FK0, g_Ph, brow0, tid);
    if (tid < 32) cpa16(sb + FQA0 + tid * 16, g_qa + brow0 + tid * 4);
    CP_COMMIT();
    CP_WAIT0();
    __syncthreads();

    float o[16][4];
    #pragma unroll
    for (int n = 0; n < 16; n++)
        #pragma unroll
        for (int u = 0; u < 4; u++) o[n][u] = 0.f;
    float lsum0 = 0.f, lsum1 = 0.f;

    for (int jt = 0; jt < 8; jt++) {
        const int cur = jt & 1;
        const uint32_t KH = sb + (cur ? FK1 : FK0);
        const float* qas = (const float*)(smem + (cur ? FQA1 : FQA0));

        if (jt < 7) {
            copy_tile(sb + (cur ? FK0 : FK1), g_Ph, brow0 + (jt + 1) * 128, tid);
            if (tid < 32)
                cpa16(sb + (cur ? FQA0 : FQA1) + tid * 16, g_qa + brow0 + (jt + 1) * 128 + tid * 4);
            CP_COMMIT();
        }

        // ---- S = (Qh + Ql) @ Kh^T, k-tile outer ----
        float s[16][4];
        #pragma unroll
        for (int n = 0; n < 16; n++)
            #pragma unroll
            for (int u = 0; u < 4; u++) s[n][u] = 0.f;

        #pragma unroll
        for (int kt = 0; kt < 8; kt++) {
            const int arow = wm * 16 + ((lg & 1) << 3) + li;
            const int acol = kt * 16 + ((lg >> 1) << 3);
            uint32_t ah[4], al[4];
            ldsm_x4(ah, sb + FQH + (arow * LDT + acol) * 2);
            ldsm_x4(al, sb + FQL + (arow * LDT + acol) * 2);

            const int brw = ((lg >> 1) << 3) + li;
            const int bcl = kt * 16 + ((lg & 1) << 3);
            uint32_t bh[8][4];
            #pragma unroll
            for (int jp = 0; jp < 8; jp++)
                ldsm_x4(bh[jp], KH + ((jp * 16 + brw) * LDT + bcl) * 2);
            #pragma unroll
            for (int jp = 0; jp < 8; jp++) {
                mma_bf16(s[2 * jp],     ah, bh[jp]);
                mma_bf16(s[2 * jp + 1], ah, bh[jp] + 2);
            }
            #pragma unroll
            for (int jp = 0; jp < 8; jp++) {
                mma_bf16(s[2 * jp],     al, bh[jp]);
                mma_bf16(s[2 * jp + 1], al, bh[jp] + 2);
            }
        }

        // ---- exp (+qa col bias), pack probs (bf16, 1-term PV) ----
        uint32_t ph[8][4];
        #pragma unroll
        for (int jn = 0; jn < 16; jn++) {
            int cb = jn * 8 + qc2;
            float q0 = qas[cb], q1 = qas[cb + 1];
            float p0 = __expf(s[jn][0] + q0);
            float p1 = __expf(s[jn][1] + q1);
            float p2 = __expf(s[jn][2] + q0);
            float p3 = __expf(s[jn][3] + q1);
            lsum0 += p0 + p1;
            lsum1 += p2 + p3;
            int kt = jn >> 1, hv = (jn & 1) << 1;
            ph[kt][hv]     = cvt2(p1, p0);
            ph[kt][hv + 1] = cvt2(p3, p2);
        }

        // ---- O += P @ V (1-term: ph x Kh; V == K tile via trans ldsm) ----
        #pragma unroll
        for (int kt = 0; kt < 8; kt++) {
            const int brw = kt * 16 + ((lg & 1) << 3) + li;
            const int bcl = (lg >> 1) << 3;
            uint32_t bh[8][4];
            #pragma unroll
            for (int dp = 0; dp < 8; dp++)
                ldsm_x4t(bh[dp], KH + (brw * LDT + dp * 16 + bcl) * 2);
            #pragma unroll
            for (int dp = 0; dp < 8; dp++) {
                mma_bf16(o[2 * dp],     ph[kt], bh[dp]);
                mma_bf16(o[2 * dp + 1], ph[kt], bh[dp] + 2);
            }
        }

        CP_WAIT0();
        __syncthreads();
    }

    // ---- normalize and emit itr as mlp A-fragments (g_Xf kb 8..15) ----
    lsum0 += __shfl_xor_sync(0xffffffffu, lsum0, 1);
    lsum0 += __shfl_xor_sync(0xffffffffu, lsum0, 2);
    lsum1 += __shfl_xor_sync(0xffffffffu, lsum1, 1);
    lsum1 += __shfl_xor_sync(0xffffffffu, lsum1, 2);
    float inv0 = 1.f / lsum0, inv1 = 1.f / lsum1;
    const size_t rbg = (brow0 + i0) / 16 + wm;
    #pragma unroll
    for (int kb = 0; kb < 8; kb++) {
        uint32_t h0, l0, h1, l1, h2, l2, h3, l3;
        split2(o[2 * kb][0] * inv0,     o[2 * kb][1] * inv0,     h0, l0);
        split2(o[2 * kb][2] * inv1,     o[2 * kb][3] * inv1,     h1, l1);
        split2(o[2 * kb + 1][0] * inv0, o[2 * kb + 1][1] * inv0, h2, l2);
        split2(o[2 * kb + 1][2] * inv1, o[2 * kb + 1][3] * inv1, h3, l3);
        size_t off = ((rbg * 16 + 8 + kb) * 32 + lane) * 8;
        *(uint4*)(g_Xf + off)     = make_uint4(h0, h1, h2, h3);
        *(uint4*)(g_Xf + off + 4) = make_uint4(l0, l1, l2, l3);
    }
}

// ===========================================================================
// Fragment-direct fused gated MLP: no smem, no barriers. 256 threads,
// 8 warps = 4 row-blocks x 2 n-halves. Software-pipelined register
// double-buffers for W and A fragments. 3-term split kept (2-term would
// put output error ~9e-4, too close to the 1e-3 threshold).
// ===========================================================================
__global__ __launch_bounds__(256, 1)
void mlp_frag(const float* __restrict__ P,
              const float* __restrict__ b1, const float* __restrict__ b2,
              const float* __restrict__ b3, float* __restrict__ out) {
    const int tid = threadIdx.x, lane = tid & 31, wid = tid >> 5;
    const int rbl = wid & 3, wn = wid >> 2;
    const int qr = lane >> 2, qc2 = (lane & 3) << 1;
    const size_t rb = (size_t)blockIdx.x * 4 + rbl;

    const uint32_t* wb0 = g_Wf + (size_t)wn * 1024 + lane * 4;   // + g*32768 + kb*2048 + nf*128
    const uint32_t* xb0 = g_Xf + (rb * 16 * 32 + lane) * 8;      // + kb*256

    float acc[3][8][4];
    #pragma unroll
    for (int g = 0; g < 3; g++)
        #pragma unroll
        for (int n = 0; n < 8; n++)
            #pragma unroll
            for (int u = 0; u < 4; u++) acc[g][n][u] = 0.f;

    uint4 wv[2][8];
    uint4 av[2][2];

    av[0][0] = *(const uint4*)(xb0);
    av[0][1] = *(const uint4*)(xb0 + 4);
    #pragma unroll
    for (int nf = 0; nf < 8; nf++)
        wv[0][nf] = *(const uint4*)(wb0 + nf * 128);

    #pragma unroll
    for (int blk = 0; blk < 48; blk++) {
        const int kb = blk / 3, g = blk - 3 * kb;
        if (g == 0 && kb < 15) {
            const uint32_t* xs = xb0 + (kb + 1) * 256;
            av[(kb + 1) & 1][0] = *(const uint4*)(xs);
            av[(kb + 1) & 1][1] = *(const uint4*)(xs + 4);
        }
        if (blk < 47) {
            const int nkb = (blk + 1) / 3, ng = (blk + 1) - 3 * nkb;
            const uint32_t* ws = wb0 + (size_t)ng * 32768 + nkb * 2048;
            #pragma unroll
            for (int nf = 0; nf < 8; nf++)
                wv[(blk + 1) & 1][nf] = *(const uint4*)(ws + nf * 128);
        }
        const uint32_t* ah = (const uint32_t*)&av[kb & 1][0];
        const uint32_t* al = (const uint32_t*)&av[kb & 1][1];
        const uint4* wc = wv[blk & 1];
        #pragma unroll
        for (int nf = 0; nf < 8; nf++) {
            uint32_t bh[2] = { wc[nf].x, wc[nf].y };
            mma_bf16(acc[g][nf], ah, bh);
        }
        #pragma unroll
        for (int nf = 0; nf < 8; nf++) {
            uint32_t bh[2] = { wc[nf].x, wc[nf].y };
            mma_bf16(acc[g][nf], al, bh);
        }
        #pragma unroll
        for (int nf = 0; nf < 8; nf++) {
            uint32_t bl[2] = { wc[nf].z, wc[nf].w };
            mma_bf16(acc[g][nf], ah, bl);
        }
    }

    // ---- epilogue: out = sigmoid(a2+b2)*P + sigmoid(a3+b3)*tanh(a1+b1) ----
    #pragma unroll
    for (int n = 0; n < 8; n++) {
        int c = wn * 64 + n * 8 + qc2;
        float bb1x = b1[c], bb1y = b1[c + 1];
        float bb2x = b2[c], bb2y = b2[c + 1];
        float bb3x = b3[c], bb3y = b3[c + 1];
        #pragma unroll
        for (int half = 0; half < 2; half++) {
            size_t r = rb * 16 + qr + half * 8;
            float2 pv = *(const float2*)(P + r * Dd + c);
            float a1x = acc[0][n][half * 2], a1y = acc[0][n][half * 2 + 1];
            float a2x = acc[1][n][half * 2], a2y = acc[1][n][half * 2 + 1];
            float a3x = acc[2][n][half * 2], a3y = acc[2][n][half * 2 + 1];
            float zx = tanhf(a1x + bb1x), zy = tanhf(a1y + bb1y);
            float rx = 1.f / (1.f + __expf(-(a2x + bb2x)));
            float ry = 1.f / (1.f + __expf(-(a2y + bb2y)));
            float fx = 1.f / (1.f + __expf(-(a3x + bb3x)));
            float fy = 1.f / (1.f + __expf(-(a3y + bb3y)));
            *(float2*)(out + r * Dd + c) =
                make_float2(rx * pv.x + fx * zx, ry * pv.y + fy * zy);
        }
    }
}

// ===========================================================================
extern "C" void kernel_launch(void* const* d_in, const int* in_sizes, int n_in,
                              void* d_out, int out_size) {
    const float* P  = (const float*)d_in[0];
    const float* w  = (const float*)d_in[1];
    const float* w1 = (const float*)d_in[2];
    const float* w2 = (const float*)d_in[3];
    const float* w3 = (const float*)d_in[4];
    const float* b1 = (const float*)d_in[5];
    const float* b2 = (const float*)d_in[6];
    const float* b3 = (const float*)d_in[7];
    float* out = (float*)d_out;

    cudaFuncSetAttribute(flash_hmma, cudaFuncAttributeMaxDynamicSharedMemorySize, FTOT);

    wsplit_frag<<<96, 256>>>(w1, w2, w3);
    prep_kernel<<<NROWS / 8, 256>>>(P, w);
    xfrag_p_kernel<<<NROWS / 16, 256>>>(P);

    dim3 fg(Nn / 128, Bsz);
    flash_hmma<<<fg, 256, FTOT>>>();

    mlp_frag<<<NROWS / 64, 256>>>(P, b1, b2, b3, out);
}

// round 12
// speedup vs baseline: 2.3569x; 1.1247x over previous
#include <cuda_runtime.h>
#include <cuda_bf16.h>
#include <cstdint>
#include <math.h>

#define Bsz 32
#define Nn  1024
#define Dd  128
#define NROWS (Bsz*Nn)

// Scratch (device globals: allocation-free rule). u32 = bf16x2 pairs.
__device__ float    g_qa[NROWS];             // qa[j] = P[j].wa
__device__ uint32_t g_Qh[NROWS * 64];        // (P*wc) hi  (flash Q plane)
__device__ uint32_t g_Ql[NROWS * 64];        // (P*wc) lo
__device__ uint32_t g_Ph[NROWS * 64];        // P hi       (flash K/V plane)
// X = [P | itr] in A-fragment-major layout for mlp:
// index ((rb*16 + kb)*32 + lane)*8 : [0..3] = hi a0..a3, [4..7] = lo a0..a3
__device__ uint32_t g_Xf[(NROWS / 16) * 16 * 32 * 8];
// W (hi only) in B-fragment-major layout:
// index (((g*16+kb)*16+nb)*32+lane)*2 : {w0 hi, w1 hi}
__device__ uint32_t g_Wf[3 * 16 * 16 * 32 * 2];

// ===========================================================================
// helpers
// ===========================================================================
__device__ __forceinline__ uint32_t smem_u32(const void* p) {
    uint32_t a;
    asm("{ .reg .u64 t; cvta.to.shared.u64 t, %1; cvt.u32.u64 %0, t; }" : "=r"(a) : "l"(p));
    return a;
}
__device__ __forceinline__ void ldsm_x4(uint32_t a[4], uint32_t addr) {
    asm volatile("ldmatrix.sync.aligned.m8n8.x4.shared.b16 {%0,%1,%2,%3}, [%4];"
        : "=r"(a[0]), "=r"(a[1]), "=r"(a[2]), "=r"(a[3]) : "r"(addr));
}
__device__ __forceinline__ void ldsm_x4t(uint32_t a[4], uint32_t addr) {
    asm volatile("ldmatrix.sync.aligned.m8n8.x4.trans.shared.b16 {%0,%1,%2,%3}, [%4];"
        : "=r"(a[0]), "=r"(a[1]), "=r"(a[2]), "=r"(a[3]) : "r"(addr));
}
__device__ __forceinline__ void mma_bf16(float c[4], const uint32_t a[4], const uint32_t b[2]) {
    asm volatile("mma.sync.aligned.m16n8k16.row.col.f32.bf16.bf16.f32 "
        "{%0,%1,%2,%3}, {%4,%5,%6,%7}, {%8,%9}, {%0,%1,%2,%3};"
        : "+f"(c[0]), "+f"(c[1]), "+f"(c[2]), "+f"(c[3])
        : "r"(a[0]), "r"(a[1]), "r"(a[2]), "r"(a[3]), "r"(b[0]), "r"(b[1]));
}
__device__ __forceinline__ void split2(float x, float y, uint32_t& h, uint32_t& l) {
    __nv_bfloat16 hx = __float2bfloat16_rn(x), hy = __float2bfloat16_rn(y);
    __nv_bfloat162 hv = __halves2bfloat162(hx, hy);
    h = *(uint32_t*)&hv;
    __nv_bfloat162 lv = __halves2bfloat162(
        __float2bfloat16_rn(x - __bfloat162float(hx)),
        __float2bfloat16_rn(y - __bfloat162float(hy)));
    l = *(uint32_t*)&lv;
}
// pack (lo,hi) floats -> bf16x2 in one cvt (first src -> HIGH half)
__device__ __forceinline__ uint32_t cvt2(float hi, float lo) {
    uint32_t d;
    asm("cvt.rn.bf16x2.f32 %0, %1, %2;" : "=r"(d) : "f"(hi), "f"(lo));
    return d;
}
__device__ __forceinline__ void cpa16(uint32_t dst, const void* src) {
    asm volatile("cp.async.cg.shared.global [%0], [%1], 16;" :: "r"(dst), "l"(src));
}
#define CP_COMMIT()  asm volatile("cp.async.commit_group;" ::: "memory")
#define CP_WAIT0()   asm volatile("cp.async.wait_group 0;" ::: "memory")

// ===========================================================================
// prep: per row -> qa dot, and bf16 planes: Ph (K/V), Qh/Ql (Q = P*wc)
// ===========================================================================
__global__ void prep_kernel(const float* __restrict__ P, const float* __restrict__ w) {
    const int row  = blockIdx.x * 8 + (threadIdx.x >> 5);
    const int lane = threadIdx.x & 31;
    const float4 p  = *(const float4*)(P + (size_t)row * Dd + lane * 4);
    const float4 wa = *(const float4*)(w + lane * 4);
    const float4 wc = *(const float4*)(w + 2 * Dd + lane * 4);
    float s = p.x * wa.x + p.y * wa.y + p.z * wa.z + p.w * wa.w;
    #pragma unroll
    for (int off = 16; off > 0; off >>= 1) s += __shfl_xor_sync(0xffffffffu, s, off);
    if (lane == 0) g_qa[row] = s;
    const size_t o = (size_t)row * 64 + lane * 2;
    uint32_t h, l;
    g_Ph[o]     = cvt2(p.y, p.x);
    g_Ph[o + 1] = cvt2(p.w, p.z);
    split2(p.x * wc.x, p.y * wc.y, h, l); g_Qh[o] = h;     g_Ql[o] = l;
    split2(p.z * wc.z, p.w * wc.w, h, l); g_Qh[o + 1] = h; g_Ql[o + 1] = l;
}

// X-fragment P part: block = row-block rb, warp = k-tile kb (0..7)
__global__ void xfrag_p_kernel(const float* __restrict__ P) {
    const int rb   = blockIdx.x;
    const int kb   = threadIdx.x >> 5;
    const int lane = threadIdx.x & 31;
    const int r0 = rb * 16 + (lane >> 2);
    const int c0 = kb * 16 + (lane & 3) * 2;
    const float* base = P + (size_t)r0 * Dd;
    float2 v00 = *(const float2*)(base + c0);
    float2 v10 = *(const float2*)(base + 8 * Dd + c0);
    float2 v01 = *(const float2*)(base + c0 + 8);
    float2 v11 = *(const float2*)(base + 8 * Dd + c0 + 8);
    uint32_t h0, l0, h1, l1, h2, l2, h3, l3;
    split2(v00.x, v00.y, h0, l0);
    split2(v10.x, v10.y, h1, l1);
    split2(v01.x, v01.y, h2, l2);
    split2(v11.x, v11.y, h3, l3);
    size_t off = (((size_t)rb * 16 + kb) * 32 + lane) * 8;
    *(uint4*)(g_Xf + off)     = make_uint4(h0, h1, h2, h3);
    *(uint4*)(g_Xf + off + 4) = make_uint4(l0, l1, l2, l3);
}

// W B-fragment-major split (hi plane only): idx = ((g*16+kb)*16+nb)*32+lane
__global__ void wsplit_frag(const float* __restrict__ w1, const float* __restrict__ w2,
                            const float* __restrict__ w3) {
    int idx = blockIdx.x * 256 + threadIdx.x;       // 24576 total
    if (idx >= 24576) return;
    int lane = idx & 31;
    int kb = (idx >> 9) & 15;
    int g  = idx >> 13;
    int nb = (idx >> 5) & 15;
    const float* W = (g == 0) ? w1 : (g == 1) ? w2 : w3;
    int k0 = kb * 16 + (lane & 3) * 2;
    int n  = nb * 8 + (lane >> 2);
    float x0 = W[k0 * 128 + n],       x1 = W[(k0 + 1) * 128 + n];
    float x2 = W[(k0 + 8) * 128 + n], x3 = W[(k0 + 9) * 128 + n];
    *(uint2*)(g_Wf + (size_t)idx * 2) = make_uint2(cvt2(x1, x0), cvt2(x3, x2));
}

// ===========================================================================
// HMMA flash attention (BM=128, BN=128, 256 thr). Operand planes precomputed;
// K tiles (single hi-plane) double-buffered via cp.async.
// S = (Qh+Ql) @ Kh^T (2-term); PV = 1-term bf16.
// Epilogue writes itr directly as mlp A-fragments (g_Xf kb 8..15).
// ===========================================================================
#define LDT 136
#define FQH  0
#define FQL  34816
#define FK0  69632            // KH only (34816)
#define FK1  104448
#define FQA0 139264
#define FQA1 139776
#define FTOT 140288

__device__ __forceinline__ void copy_tile_pair(uint32_t dstHi, uint32_t dstLo,
        const uint32_t* __restrict__ srcHi, const uint32_t* __restrict__ srcLo,
        size_t grow0, int tid) {
    #pragma unroll
    for (int t = 0; t < 8; t++) {
        int idx = tid + t * 256;             // 2048 16B-chunks (128 rows x 16)
        int r = idx >> 4, c8 = idx & 15;
        uint32_t doff = (uint32_t)(r * LDT + c8 * 8) * 2;
        cpa16(dstHi + doff, srcHi + (grow0 + r) * 64 + c8 * 4);
        cpa16(dstLo + doff, srcLo + (grow0 + r) * 64 + c8 * 4);
    }
}
__device__ __forceinline__ void copy_tile(uint32_t dst,
        const uint32_t* __restrict__ src, size_t grow0, int tid) {
    #pragma unroll
    for (int t = 0; t < 8; t++) {
        int idx = tid + t * 256;
        int r = idx >> 4, c8 = idx & 15;
        cpa16(dst + (uint32_t)(r * LDT + c8 * 8) * 2, src + (grow0 + r) * 64 + c8 * 4);
    }
}

__global__ __launch_bounds__(256, 1)
void flash_hmma() {
    extern __shared__ char smem[];
    const uint32_t sb = smem_u32(smem);
    const int tid = threadIdx.x, lane = tid & 31, wm = tid >> 5;
    const int b = blockIdx.y, i0 = blockIdx.x * 128;
    const int lg = lane >> 3, li = lane & 7;
    const int qc2 = (lane & 3) << 1;
    const size_t brow0 = (size_t)b * Nn;

    copy_tile_pair(sb + FQH, sb + FQL, g_Qh, g_Ql, brow0 + i0, tid);
    copy_tile(sb + FK0, g_Ph, brow0, tid);
    if (tid < 32) cpa16(sb + FQA0 + tid * 16, g_qa + brow0 + tid * 4);
    CP_COMMIT();
    CP_WAIT0();
    __syncthreads();

    float o[16][4];
    #pragma unroll
    for (int n = 0; n < 16; n++)
        #pragma unroll
        for (int u = 0; u < 4; u++) o[n][u] = 0.f;
    float lsum0 = 0.f, lsum1 = 0.f;

    for (int jt = 0; jt < 8; jt++) {
        const int cur = jt & 1;
        const uint32_t KH = sb + (cur ? FK1 : FK0);
        const float* qas = (const float*)(smem + (cur ? FQA1 : FQA0));

        if (jt < 7) {
            copy_tile(sb + (cur ? FK0 : FK1), g_Ph, brow0 + (jt + 1) * 128, tid);
            if (tid < 32)
                cpa16(sb + (cur ? FQA0 : FQA1) + tid * 16, g_qa + brow0 + (jt + 1) * 128 + tid * 4);
            CP_COMMIT();
        }

        // ---- S = (Qh + Ql) @ Kh^T, k-tile outer ----
        float s[16][4];
        #pragma unroll
        for (int n = 0; n < 16; n++)
            #pragma unroll
            for (int u = 0; u < 4; u++) s[n][u] = 0.f;

        #pragma unroll
        for (int kt = 0; kt < 8; kt++) {
            const int arow = wm * 16 + ((lg & 1) << 3) + li;
            const int acol = kt * 16 + ((lg >> 1) << 3);
            uint32_t ah[4], al[4];
            ldsm_x4(ah, sb + FQH + (arow * LDT + acol) * 2);
            ldsm_x4(al, sb + FQL + (arow * LDT + acol) * 2);

            const int brw = ((lg >> 1) << 3) + li;
            const int bcl = kt * 16 + ((lg & 1) << 3);
            uint32_t bh[8][4];
            #pragma unroll
            for (int jp = 0; jp < 8; jp++)
                ldsm_x4(bh[jp], KH + ((jp * 16 + brw) * LDT + bcl) * 2);
            #pragma unroll
            for (int jp = 0; jp < 8; jp++) {
                mma_bf16(s[2 * jp],     ah, bh[jp]);
                mma_bf16(s[2 * jp + 1], ah, bh[jp] + 2);
            }
            #pragma unroll
            for (int jp = 0; jp < 8; jp++) {
                mma_bf16(s[2 * jp],     al, bh[jp]);
                mma_bf16(s[2 * jp + 1], al, bh[jp] + 2);
            }
        }

        // ---- exp (+qa col bias), pack probs (bf16, 1-term PV) ----
        uint32_t ph[8][4];
        #pragma unroll
        for (int jn = 0; jn < 16; jn++) {
            int cb = jn * 8 + qc2;
            float q0 = qas[cb], q1 = qas[cb + 1];
            float p0 = __expf(s[jn][0] + q0);
            float p1 = __expf(s[jn][1] + q1);
            float p2 = __expf(s[jn][2] + q0);
            float p3 = __expf(s[jn][3] + q1);
            lsum0 += p0 + p1;
            lsum1 += p2 + p3;
            int kt = jn >> 1, hv = (jn & 1) << 1;
            ph[kt][hv]     = cvt2(p1, p0);
            ph[kt][hv + 1] = cvt2(p3, p2);
        }

        // ---- O += P @ V (1-term: ph x Kh; V == K tile via trans ldsm) ----
        #pragma unroll
        for (int kt = 0; kt < 8; kt++) {
            const int brw = kt * 16 + ((lg & 1) << 3) + li;
            const int bcl = (lg >> 1) << 3;
            uint32_t bh[8][4];
            #pragma unroll
            for (int dp = 0; dp < 8; dp++)
                ldsm_x4t(bh[dp], KH + (brw * LDT + dp * 16 + bcl) * 2);
            #pragma unroll
            for (int dp = 0; dp < 8; dp++) {
                mma_bf16(o[2 * dp],     ph[kt], bh[dp]);
                mma_bf16(o[2 * dp + 1], ph[kt], bh[dp] + 2);
            }
        }

        CP_WAIT0();
        __syncthreads();
    }

    // ---- normalize and emit itr as mlp A-fragments (g_Xf kb 8..15) ----
    lsum0 += __shfl_xor_sync(0xffffffffu, lsum0, 1);
    lsum0 += __shfl_xor_sync(0xffffffffu, lsum0, 2);
    lsum1 += __shfl_xor_sync(0xffffffffu, lsum1, 1);
    lsum1 += __shfl_xor_sync(0xffffffffu, lsum1, 2);
    float inv0 = 1.f / lsum0, inv1 = 1.f / lsum1;
    const size_t rbg = (brow0 + i0) / 16 + wm;
    #pragma unroll
    for (int kb = 0; kb < 8; kb++) {
        uint32_t h0, l0, h1, l1, h2, l2, h3, l3;
        split2(o[2 * kb][0] * inv0,     o[2 * kb][1] * inv0,     h0, l0);
        split2(o[2 * kb][2] * inv1,     o[2 * kb][3] * inv1,     h1, l1);
        split2(o[2 * kb + 1][0] * inv0, o[2 * kb + 1][1] * inv0, h2, l2);
        split2(o[2 * kb + 1][2] * inv1, o[2 * kb + 1][3] * inv1, h3, l3);
        size_t off = ((rbg * 16 + 8 + kb) * 32 + lane) * 8;
        *(uint4*)(g_Xf + off)     = make_uint4(h0, h1, h2, h3);
        *(uint4*)(g_Xf + off + 4) = make_uint4(l0, l1, l2, l3);
    }
}

// ===========================================================================
// Fragment-direct fused gated MLP: no smem, no barriers. 256 threads,
// 8 warps = 4 row-blocks x 2 n-halves. 2-term split: (Xh+Xl) @ Wh (W residual
// dropped per recalibrated error budget). W fragments uint2, triple-buffered
// (prefetch 2 blocks ahead to cover L2 latency); A double-buffered.
// ===========================================================================
__global__ __launch_bounds__(256, 1)
void mlp_frag(const float* __restrict__ P,
              const float* __restrict__ b1, const float* __restrict__ b2,
              const float* __restrict__ b3, float* __restrict__ out) {
    const int tid = threadIdx.x, lane = tid & 31, wid = tid >> 5;
    const int rbl = wid & 3, wn = wid >> 2;
    const int qr = lane >> 2, qc2 = (lane & 3) << 1;
    const size_t rb = (size_t)blockIdx.x * 4 + rbl;

    const uint32_t* wb0 = g_Wf + (size_t)wn * 512 + lane * 2;    // + g*16384 + kb*1024 + nf*64
    const uint32_t* xb0 = g_Xf + (rb * 16 * 32 + lane) * 8;      // + kb*256

    float acc[3][8][4];
    #pragma unroll
    for (int g = 0; g < 3; g++)
        #pragma unroll
        for (int n = 0; n < 8; n++)
            #pragma unroll
            for (int u = 0; u < 4; u++) acc[g][n][u] = 0.f;

    uint2 wv[3][8];
    uint4 av[2][2];

    // prologue: A(kb=0); W blk0=(kb0,g0), blk1=(kb0,g1)
    av[0][0] = *(const uint4*)(xb0);
    av[0][1] = *(const uint4*)(xb0 + 4);
    #pragma unroll
    for (int nf = 0; nf < 8; nf++)
        wv[0][nf] = *(const uint2*)(wb0 + nf * 64);
    #pragma unroll
    for (int nf = 0; nf < 8; nf++)
        wv[1][nf] = *(const uint2*)(wb0 + 16384 + nf * 64);

    #pragma unroll
    for (int blk = 0; blk < 48; blk++) {
        const int kb = blk / 3, g = blk - 3 * kb;
        // prefetch A for kb+1 at the start of each kb
        if (g == 0 && kb < 15) {
            const uint32_t* xs = xb0 + (kb + 1) * 256;
            av[(kb + 1) & 1][0] = *(const uint4*)(xs);
            av[(kb + 1) & 1][1] = *(const uint4*)(xs + 4);
        }
        // prefetch W 2 blocks ahead
        if (blk < 46) {
            const int nblk = blk + 2;
            const int nkb = nblk / 3, ng = nblk - 3 * nkb;
            const uint32_t* ws = wb0 + (size_t)ng * 16384 + nkb * 1024;
            #pragma unroll
            for (int nf = 0; nf < 8; nf++)
                wv[nblk % 3][nf] = *(const uint2*)(ws + nf * 64);
        }
        const uint32_t* ah = (const uint32_t*)&av[kb & 1][0];
        const uint32_t* al = (const uint32_t*)&av[kb & 1][1];
        const uint2* wc = wv[blk % 3];
        #pragma unroll
        for (int nf = 0; nf < 8; nf++) {
            uint32_t bh[2] = { wc[nf].x, wc[nf].y };
            mma_bf16(acc[g][nf], ah, bh);
        }
        #pragma unroll
        for (int nf = 0; nf < 8; nf++) {
            uint32_t bh[2] = { wc[nf].x, wc[nf].y };
            mma_bf16(acc[g][nf], al, bh);
        }
    }

    // ---- epilogue: out = sigmoid(a2+b2)*P + sigmoid(a3+b3)*tanh(a1+b1) ----
    #pragma unroll
    for (int n = 0; n < 8; n++) {
        int c = wn * 64 + n * 8 + qc2;
        float bb1x = b1[c], bb1y = b1[c + 1];
        float bb2x = b2[c], bb2y = b2[c + 1];
        float bb3x = b3[c], bb3y = b3[c + 1];
        #pragma unroll
        for (int half = 0; half < 2; half++) {
            size_t r = rb * 16 + qr + half * 8;
            float2 pv = *(const float2*)(P + r * Dd + c);
            float a1x = acc[0][n][half * 2], a1y = acc[0][n][half * 2 + 1];
            float a2x = acc[1][n][half * 2], a2y = acc[1][n][half * 2 + 1];
            float a3x = acc[2][n][half * 2], a3y = acc[2][n][half * 2 + 1];
            float zx = tanhf(a1x + bb1x), zy = tanhf(a1y + bb1y);
            float rx = 1.f / (1.f + __expf(-(a2x + bb2x)));
            float ry = 1.f / (1.f + __expf(-(a2y + bb2y)));
            float fx = 1.f / (1.f + __expf(-(a3x + bb3x)));
            float fy = 1.f / (1.f + __expf(-(a3y + bb3y)));
            *(float2*)(out + r * Dd + c) =
                make_float2(rx * pv.x + fx * zx, ry * pv.y + fy * zy);
        }
    }
}

// ===========================================================================
extern "C" void kernel_launch(void* const* d_in, const int* in_sizes, int n_in,
                              void* d_out, int out_size) {
    const float* P  = (const float*)d_in[0];
    const float* w  = (const float*)d_in[1];
    const float* w1 = (const float*)d_in[2];
    const float* w2 = (const float*)d_in[3];
    const float* w3 = (const float*)d_in[4];
    const float* b1 = (const float*)d_in[5];
    const float* b2 = (const float*)d_in[6];
    const float* b3 = (const float*)d_in[7];
    float* out = (float*)d_out;

    cudaFuncSetAttribute(flash_hmma, cudaFuncAttributeMaxDynamicSharedMemorySize, FTOT);

    wsplit_frag<<<96, 256>>>(w1, w2, w3);
    prep_kernel<<<NROWS / 8, 256>>>(P, w);
    xfrag_p_kernel<<<NROWS / 16, 256>>>(P);

    dim3 fg(Nn / 128, Bsz);
    flash_hmma<<<fg, 256, FTOT>>>();

    mlp_frag<<<NROWS / 64, 256>>>(P, b1, b2, b3, out);
}